// round 3
// baseline (speedup 1.0000x reference)
#include <cuda_runtime.h>

#define NBIN 512
#define WIN 1022
#define T_IN 127
#define BATCH 64
#define NF (BATCH * T_IN)       // 8128
#define HOP 256
#define T_OUT 62
#define NF3 (BATCH * T_OUT)     // 3968
#define SIG_STRIDE 16672
#define L_OUT 16670
#define J_EVEN 16608

// ---------------- device scratch ----------------
__device__ float  g_frames[NF * 512];
__device__ float  g_tail[BATCH * 32];
__device__ float  g_sig[BATCH * SIG_STRIDE];
__device__ float  g_W1c[512 * 512];          // irfft even-n cos plane, synth folded
__device__ float  g_W1s[512 * 512];          // irfft even-n -sin plane, synth folded
__device__ float2 g_W3[1024 * 512];          // rfft: (win*cos, -win*sin) [n][k]
__device__ float2 g_trig[1022];              // (cos(pi j/511), sin(pi j/511))
__device__ float  g_synth[WIN];
__device__ float  g_window[1024];

// ---------------- packed f32x2 helpers ----------------
__device__ __forceinline__ void fma2(unsigned long long& d, unsigned long long a, unsigned long long b) {
    asm("fma.rn.f32x2 %0, %1, %2, %0;" : "+l"(d) : "l"(a), "l"(b));
}
__device__ __forceinline__ float2 upk(unsigned long long v) {
    float2 f;
    asm("mov.b64 {%0, %1}, %2;" : "=f"(f.x), "=f"(f.y) : "l"(v));
    return f;
}

// ---------------- setup ----------------
__global__ void k_setup() {
    __shared__ float sd[256];
    int tid = threadIdx.x;
    double s = 0.0;
    for (int r = 0; r < 4; r++) {
        int i = r * 256 + tid;
        if (i < WIN) {
            double w = 0.5 - 0.5 * cospi(2.0 * (double)i / 1022.0);
            s += w * w;
        }
    }
    sd[tid] = (float)s;
    __syncthreads();
    for (int n = tid; n < 1024; n += 256) {
        if (n < WIN) {
            double w = 0.5 - 0.5 * cospi(2.0 * (double)n / 1022.0);
            g_window[n] = (float)w;
            g_synth[n] = (float)(w / (double)sd[n & 255]);
        } else {
            g_window[n] = 0.0f;
        }
    }
}

__global__ void k_fill_trig() {
    int j = blockIdx.x * blockDim.x + threadIdx.x;
    if (j < 1022) {
        float sn, cs;
        sincospif((float)j / 511.0f, &sn, &cs);
        g_trig[j] = make_float2(cs, sn);
    }
}

// W1 with synth2 folded: W1c[k][m] = coef*cos(2pi k m/511)*synth[2m]
__global__ void k_fill_w1() {
    int k = blockIdx.x;
    const float invN = 1.0f / 1022.0f;
    for (int m = threadIdx.x; m < 512; m += blockDim.x) {
        float vc = 0.0f, vs = 0.0f;
        if (m < 511) {
            float sv = g_synth[2 * m];
            if (k == 0 || k == 511) {
                vc = invN * sv;
            } else {
                int r = (k * m) % 511;
                float2 t = g_trig[2 * r];
                vc = 2.0f * invN * t.x * sv;
                vs = -2.0f * invN * t.y * sv;
            }
        }
        g_W1c[k * 512 + m] = vc;
        g_W1s[k * 512 + m] = vs;
    }
}

// W3 interleaved with window folded: (win[n]*cos, -win[n]*sin)
__global__ void k_fill_w3() {
    int n = blockIdx.x;
    float w = g_window[n];  // 0 for n >= 1022
    for (int k = threadIdx.x; k < 512; k += blockDim.x) {
        float2 v = make_float2(0.0f, 0.0f);
        if (n < WIN) {
            int j = (n * k) % WIN;
            float2 t = g_trig[j];
            v = make_float2(w * t.x, -w * t.y);
        }
        g_W3[n * 512 + k] = v;
    }
}

// ---------------- pass 1: irfft at even samples, 128x128 tile, 8x8/thread ----------------
#define BK1 16
__global__ __launch_bounds__(256, 2) void k_pass1(const float2* __restrict__ inF2) {
    __shared__ float2 ArD[BK1][128], AiD[BK1][128];   // duplicated (a,a)
    __shared__ float  Bc[BK1][128], Bs[BK1][128];     // synth folded
    int tid = threadIdx.x;
    int m0 = blockIdx.x * 128;
    int f0 = blockIdx.y * 128;
    int tx = tid & 15, ty = tid >> 4;

    unsigned long long acc[8][4];
#pragma unroll
    for (int i = 0; i < 8; i++)
#pragma unroll
        for (int j = 0; j < 4; j++) acc[i][j] = 0ULL;

    for (int kc = 0; kc < 512; kc += BK1) {
#pragma unroll
        for (int r = 0; r < 8; r++) {
            int e = r * 256 + tid;
            int fl = e & 127, kl = e >> 7;
            int f = min(f0 + fl, NF - 1);
            int b = f / 127, t = f - b * 127;
            float2 v = inF2[(b * 512 + kc + kl) * 127 + t];
            ArD[kl][fl] = make_float2(v.x, v.x);
            AiD[kl][fl] = make_float2(v.y, v.y);
        }
#pragma unroll
        for (int r = 0; r < 2; r++) {
            int e = r * 256 + tid;
            int q = e & 31, kl = e >> 5;
            ((float4*)&Bc[kl][0])[q] = ((const float4*)(g_W1c + (kc + kl) * 512 + m0))[q];
            ((float4*)&Bs[kl][0])[q] = ((const float4*)(g_W1s + (kc + kl) * 512 + m0))[q];
        }
        __syncthreads();
#pragma unroll
        for (int kk = 0; kk < BK1; kk++) {
            // A: 8 duplicated pairs (f = ty*4+0..3, 64+ty*4+0..3)
            ulonglong2 arL0 = ((const ulonglong2*)&ArD[kk][0])[ty * 2];
            ulonglong2 arL1 = ((const ulonglong2*)&ArD[kk][0])[ty * 2 + 1];
            ulonglong2 arH0 = ((const ulonglong2*)&ArD[kk][0])[32 + ty * 2];
            ulonglong2 arH1 = ((const ulonglong2*)&ArD[kk][0])[32 + ty * 2 + 1];
            ulonglong2 aiL0 = ((const ulonglong2*)&AiD[kk][0])[ty * 2];
            ulonglong2 aiL1 = ((const ulonglong2*)&AiD[kk][0])[ty * 2 + 1];
            ulonglong2 aiH0 = ((const ulonglong2*)&AiD[kk][0])[32 + ty * 2];
            ulonglong2 aiH1 = ((const ulonglong2*)&AiD[kk][0])[32 + ty * 2 + 1];
            // B: 4 (m,m+1) pairs per plane, m = tx*8 + {0,2,4,6}
            ulonglong2 bc01 = ((const ulonglong2*)&Bc[kk][0])[tx * 2];
            ulonglong2 bc23 = ((const ulonglong2*)&Bc[kk][0])[tx * 2 + 1];
            ulonglong2 bs01 = ((const ulonglong2*)&Bs[kk][0])[tx * 2];
            ulonglong2 bs23 = ((const ulonglong2*)&Bs[kk][0])[tx * 2 + 1];
            unsigned long long ar[8] = {arL0.x, arL0.y, arL1.x, arL1.y, arH0.x, arH0.y, arH1.x, arH1.y};
            unsigned long long ai[8] = {aiL0.x, aiL0.y, aiL1.x, aiL1.y, aiH0.x, aiH0.y, aiH1.x, aiH1.y};
            unsigned long long bcv[4] = {bc01.x, bc01.y, bc23.x, bc23.y};
            unsigned long long bsv[4] = {bs01.x, bs01.y, bs23.x, bs23.y};
#pragma unroll
            for (int i = 0; i < 8; i++) {
#pragma unroll
                for (int j = 0; j < 4; j++) {
                    fma2(acc[i][j], ar[i], bcv[j]);
                    fma2(acc[i][j], ai[i], bsv[j]);
                }
            }
        }
        __syncthreads();
    }

#pragma unroll
    for (int i = 0; i < 8; i++) {
        int f = f0 + (i < 4 ? ty * 4 + i : 64 + ty * 4 + (i - 4));
        if (f < NF) {
#pragma unroll
            for (int j = 0; j < 4; j++) {
                int m = m0 + tx * 8 + 2 * j;
                float2 v = upk(acc[i][j]);
                g_frames[f * 512 + m] = v.x;        // synth already folded in W1
                g_frames[f * 512 + m + 1] = v.y;
            }
        }
    }
}

// ---------------- pass 1b: odd tail of frame 126 (direct LUT) ----------------
__global__ void k_pass1b(const float2* __restrict__ inF2) {
    __shared__ float2 sb[512];
    __shared__ float part[31][8];
    int b = blockIdx.x;
    int tid = threadIdx.x;
    for (int k = tid; k < 512; k += 256)
        sb[k] = inF2[(b * 512 + k) * 127 + 126];
    __syncthreads();
    int ni = tid >> 3, kp = tid & 7;
    if (ni < 31) {
        int n = 961 + 2 * ni;
        float acc = 0.0f;
        for (int k = kp; k < 512; k += 8) {
            float2 x = sb[k];
            float2 t = g_trig[(n * k) % WIN];
            float coef = (k == 0 || k == 511) ? 1.0f : 2.0f;
            acc += coef * (x.x * t.x - x.y * t.y);
        }
        part[ni][kp] = acc;
    }
    __syncthreads();
    if (tid < 31) {
        float s = 0.0f;
#pragma unroll
        for (int q = 0; q < 8; q++) s += part[tid][q];
        g_tail[b * 32 + tid] = s * (1.0f / 1022.0f) * g_synth[961 + 2 * tid];
    }
}

// ---------------- pass 2: overlap-add ----------------
__global__ void k_pass2() {
    int idx = blockIdx.x * blockDim.x + threadIdx.x;
    if (idx >= BATCH * L_OUT) return;
    int b = idx / L_OUT, j = idx - b * L_OUT;
    float v;
    if (j < J_EVEN) {
        int p = 2 * j;
        int t_hi = min(126, p >> 8);
        int t_lo = max(0, p - 766) >> 8;
        float acc = 0.0f;
        for (int t = t_lo; t <= t_hi; t++) {
            int m = j - (t << 7);
            acc += g_frames[(b * 127 + t) * 512 + m];
        }
        v = acc;
    } else {
        int n = j - 15648;
        if (n & 1) v = g_tail[b * 32 + ((n - 961) >> 1)];
        else       v = g_frames[(b * 127 + 126) * 512 + (n >> 1)];
    }
    g_sig[b * SIG_STRIDE + j] = v;
}

// ---------------- pass 3: window+rfft, 128f x 64k tile, 8x4(complex)/thread ----------------
#define BK3 32
__global__ __launch_bounds__(256, 2) void k_pass3(float2* __restrict__ outF2) {
    __shared__ float2 AwD[BK3][128];   // duplicated (a,a), window folded into B
    __shared__ float2 Bcs[BK3][64];    // (w cos, -w sin)
    int tid = threadIdx.x;
    int k0 = blockIdx.x * 64;
    int f0 = blockIdx.y * 128;
    int tx = tid & 15, ty = tid >> 4;

    unsigned long long acc[8][4];
#pragma unroll
    for (int i = 0; i < 8; i++)
#pragma unroll
        for (int j = 0; j < 4; j++) acc[i][j] = 0ULL;

    for (int nc = 0; nc < 1024; nc += BK3) {
#pragma unroll
        for (int r = 0; r < 16; r++) {
            int e = r * 256 + tid;
            int fl = e & 127, nl = e >> 7;
            int f = f0 + fl;
            int b = f / 62, t = f - b * 62;
            float a = g_sig[b * SIG_STRIDE + t * 256 + nc + nl];
            AwD[nl][fl] = make_float2(a, a);
        }
#pragma unroll
        for (int r = 0; r < 4; r++) {
            int e = r * 256 + tid;
            int q = e & 31, nl = e >> 5;  // 32 float4 per row of 64 float2
            ((float4*)&Bcs[nl][0])[q] = ((const float4*)(g_W3 + (nc + nl) * 512 + k0))[q];
        }
        __syncthreads();
#pragma unroll
        for (int kk = 0; kk < BK3; kk++) {
            ulonglong2 aL0 = ((const ulonglong2*)&AwD[kk][0])[ty * 2];
            ulonglong2 aL1 = ((const ulonglong2*)&AwD[kk][0])[ty * 2 + 1];
            ulonglong2 aH0 = ((const ulonglong2*)&AwD[kk][0])[32 + ty * 2];
            ulonglong2 aH1 = ((const ulonglong2*)&AwD[kk][0])[32 + ty * 2 + 1];
            ulonglong2 b01 = ((const ulonglong2*)&Bcs[kk][0])[tx * 2];
            ulonglong2 b23 = ((const ulonglong2*)&Bcs[kk][0])[tx * 2 + 1];
            unsigned long long av[8] = {aL0.x, aL0.y, aL1.x, aL1.y, aH0.x, aH0.y, aH1.x, aH1.y};
            unsigned long long bv[4] = {b01.x, b01.y, b23.x, b23.y};
#pragma unroll
            for (int i = 0; i < 8; i++) {
#pragma unroll
                for (int j = 0; j < 4; j++) {
                    fma2(acc[i][j], av[i], bv[j]);
                }
            }
        }
        __syncthreads();
    }

#pragma unroll
    for (int i = 0; i < 8; i++) {
        int f = f0 + (i < 4 ? ty * 4 + i : 64 + ty * 4 + (i - 4));
        int b = f / 62, t = f - b * 62;
#pragma unroll
        for (int j = 0; j < 4; j++) {
            int k = k0 + tx * 4 + j;
            float2 v = upk(acc[i][j]);
            outF2[(b * 512 + k) * 62 + t] = v;
        }
    }
}

// ---------------- launch ----------------
extern "C" void kernel_launch(void* const* d_in, const int* in_sizes, int n_in,
                              void* d_out, int out_size) {
    (void)in_sizes; (void)n_in; (void)out_size;
    const float2* inF2 = (const float2*)d_in[0];
    float2* outF2 = (float2*)d_out;

    k_setup<<<1, 256>>>();
    k_fill_trig<<<4, 256>>>();
    k_fill_w1<<<512, 256>>>();
    k_fill_w3<<<1024, 256>>>();
    k_pass1<<<dim3(4, 64), 256>>>(inF2);
    k_pass1b<<<64, 256>>>(inF2);
    k_pass2<<<(BATCH * L_OUT + 255) / 256, 256>>>();
    k_pass3<<<dim3(8, 31), 256>>>(outF2);
}

// round 4
// speedup vs baseline: 1.3657x; 1.3657x over previous
#include <cuda_runtime.h>

#define NBIN 512
#define WIN 1022
#define T_IN 127
#define BATCH 64
#define NF (BATCH * T_IN)       // 8128
#define HOP 256
#define T_OUT 62
#define NF3 (BATCH * T_OUT)     // 3968
#define SIG_STRIDE 16672
#define L_OUT 16670
#define J_EVEN 16608
#define FSTR 3968

// ---------------- device scratch ----------------
__device__ float  g_frames[NF * 512];
__device__ float  g_tail[BATCH * 32];
__device__ float  g_sig[BATCH * SIG_STRIDE];
__device__ float  g_sigT[1024 * FSTR];       // transposed windowless signal [n][f]
__device__ float  g_W1c[512 * 512];          // irfft even-n cos plane, synth folded
__device__ float  g_W1s[512 * 512];          // irfft even-n -sin plane, synth folded
__device__ float  g_W3c[1024 * 512];         // rfft cos plane, window folded
__device__ float  g_W3s[1024 * 512];         // rfft -sin plane, window folded
__device__ float2 g_trig[1022];              // (cos(pi j/511), sin(pi j/511))
__device__ float  g_synth[WIN];
__device__ float  g_window[1024];

// ---------------- packed f32x2 helpers ----------------
__device__ __forceinline__ unsigned long long pk2(float lo, float hi) {
    unsigned long long r;
    asm("mov.b64 %0, {%1, %2};" : "=l"(r) : "f"(lo), "f"(hi));
    return r;
}
__device__ __forceinline__ void fma2(unsigned long long& d, unsigned long long a, unsigned long long b) {
    asm("fma.rn.f32x2 %0, %1, %2, %0;" : "+l"(d) : "l"(a), "l"(b));
}
__device__ __forceinline__ float2 upk(unsigned long long v) {
    float2 f;
    asm("mov.b64 {%0, %1}, %2;" : "=f"(f.x), "=f"(f.y) : "l"(v));
    return f;
}

// ---------------- setup ----------------
__global__ void k_setup() {
    __shared__ float sd[256];
    int tid = threadIdx.x;
    double s = 0.0;
    for (int r = 0; r < 4; r++) {
        int i = r * 256 + tid;
        if (i < WIN) {
            double w = 0.5 - 0.5 * cospi(2.0 * (double)i / 1022.0);
            s += w * w;
        }
    }
    sd[tid] = (float)s;
    __syncthreads();
    for (int n = tid; n < 1024; n += 256) {
        if (n < WIN) {
            double w = 0.5 - 0.5 * cospi(2.0 * (double)n / 1022.0);
            g_window[n] = (float)w;
            g_synth[n] = (float)(w / (double)sd[n & 255]);
        } else {
            g_window[n] = 0.0f;
        }
    }
}

__global__ void k_fill_trig() {
    int j = blockIdx.x * blockDim.x + threadIdx.x;
    if (j < 1022) {
        float sn, cs;
        sincospif((float)j / 511.0f, &sn, &cs);
        g_trig[j] = make_float2(cs, sn);
    }
}

__global__ void k_fill_w1() {
    int k = blockIdx.x;
    const float invN = 1.0f / 1022.0f;
    for (int m = threadIdx.x; m < 512; m += blockDim.x) {
        float vc = 0.0f, vs = 0.0f;
        if (m < 511) {
            float sv = g_synth[2 * m];
            if (k == 0 || k == 511) {
                vc = invN * sv;
            } else {
                int r = (k * m) % 511;
                float2 t = g_trig[2 * r];
                vc = 2.0f * invN * t.x * sv;
                vs = -2.0f * invN * t.y * sv;
            }
        }
        g_W1c[k * 512 + m] = vc;
        g_W1s[k * 512 + m] = vs;
    }
}

__global__ void k_fill_w3() {
    int n = blockIdx.x;
    float w = (n < WIN) ? g_window[n] : 0.0f;
    for (int k = threadIdx.x; k < 512; k += blockDim.x) {
        float vc = 0.0f, vs = 0.0f;
        if (n < WIN) {
            int j = (n * k) % WIN;
            float2 t = g_trig[j];
            vc = w * t.x;
            vs = -w * t.y;
        }
        g_W3c[n * 512 + k] = vc;
        g_W3s[n * 512 + k] = vs;
    }
}

// ---------------- pass 1: irfft at even samples, 128x128 tile, 8x8/thread ----------------
#define BK1 16
__global__ __launch_bounds__(256, 2) void k_pass1(const float2* __restrict__ inF2) {
    __shared__ float Ar[BK1][128], Ai[BK1][128], Bc[BK1][128], Bs[BK1][128];
    int tid = threadIdx.x;
    int m0 = blockIdx.x * 128;
    int f0 = blockIdx.y * 128;
    int tx = tid & 15, ty = tid >> 4;

    // A addressing is constant across k-chunks: base_r + kc*127
    int base_r[8];
#pragma unroll
    for (int r = 0; r < 8; r++) {
        int e = r * 256 + tid;
        int fl = e & 127, kl = e >> 7;
        int f = min(f0 + fl, NF - 1);
        int b = f / 127, t = f - b * 127;
        base_r[r] = b * (512 * 127) + kl * 127 + t;
    }
    float2 pre[8];
#pragma unroll
    for (int r = 0; r < 8; r++) pre[r] = inF2[base_r[r]];

    unsigned long long acc[8][4];
#pragma unroll
    for (int i = 0; i < 8; i++)
#pragma unroll
        for (int j = 0; j < 4; j++) acc[i][j] = 0ULL;

    for (int kc = 0; kc < 512; kc += BK1) {
#pragma unroll
        for (int r = 0; r < 8; r++) {
            int e = r * 256 + tid;
            int fl = e & 127, kl = e >> 7;
            Ar[kl][fl] = pre[r].x;
            Ai[kl][fl] = pre[r].y;
        }
#pragma unroll
        for (int r = 0; r < 2; r++) {
            int e = r * 256 + tid;
            int q = e & 31, kl = e >> 5;
            ((float4*)&Bc[kl][0])[q] = ((const float4*)(g_W1c + (kc + kl) * 512 + m0))[q];
            ((float4*)&Bs[kl][0])[q] = ((const float4*)(g_W1s + (kc + kl) * 512 + m0))[q];
        }
        __syncthreads();
        if (kc + BK1 < 512) {
#pragma unroll
            for (int r = 0; r < 8; r++) pre[r] = inF2[base_r[r] + (kc + BK1) * 127];
        }
#pragma unroll 8
        for (int kk = 0; kk < BK1; kk++) {
            float4 arL = ((const float4*)Ar[kk])[ty];
            float4 arH = ((const float4*)Ar[kk])[16 + ty];
            float4 aiL = ((const float4*)Ai[kk])[ty];
            float4 aiH = ((const float4*)Ai[kk])[16 + ty];
            float4 bcL = ((const float4*)Bc[kk])[tx];
            float4 bcH = ((const float4*)Bc[kk])[16 + tx];
            float4 bsL = ((const float4*)Bs[kk])[tx];
            float4 bsH = ((const float4*)Bs[kk])[16 + tx];
            unsigned long long bc0 = pk2(bcL.x, bcL.y), bc1 = pk2(bcL.z, bcL.w);
            unsigned long long bc2 = pk2(bcH.x, bcH.y), bc3 = pk2(bcH.z, bcH.w);
            unsigned long long bs0 = pk2(bsL.x, bsL.y), bs1 = pk2(bsL.z, bsL.w);
            unsigned long long bs2 = pk2(bsH.x, bsH.y), bs3 = pk2(bsH.z, bsH.w);
            float arv[8] = {arL.x, arL.y, arL.z, arL.w, arH.x, arH.y, arH.z, arH.w};
            float aiv[8] = {aiL.x, aiL.y, aiL.z, aiL.w, aiH.x, aiH.y, aiH.z, aiH.w};
#pragma unroll
            for (int i = 0; i < 8; i++) {
                unsigned long long ar2 = pk2(arv[i], arv[i]);
                unsigned long long ai2 = pk2(aiv[i], aiv[i]);
                fma2(acc[i][0], ar2, bc0); fma2(acc[i][0], ai2, bs0);
                fma2(acc[i][1], ar2, bc1); fma2(acc[i][1], ai2, bs1);
                fma2(acc[i][2], ar2, bc2); fma2(acc[i][2], ai2, bs2);
                fma2(acc[i][3], ar2, bc3); fma2(acc[i][3], ai2, bs3);
            }
        }
        __syncthreads();
    }

#pragma unroll
    for (int i = 0; i < 8; i++) {
        int f = f0 + (i < 4 ? ty * 4 + i : 64 + ty * 4 + (i - 4));
        if (f < NF) {
#pragma unroll
            for (int jj = 0; jj < 4; jj++) {
                int m = (jj < 2) ? (m0 + tx * 4 + 2 * jj) : (m0 + 64 + tx * 4 + 2 * (jj - 2));
                float2 v = upk(acc[i][jj]);
                g_frames[f * 512 + m] = v.x;      // synth folded in W1
                g_frames[f * 512 + m + 1] = v.y;  // col 511 is zero-plane -> writes 0
            }
        }
    }
}

// ---------------- pass 1b: odd tail of frame 126 (LUT) ----------------
__global__ void k_pass1b(const float2* __restrict__ inF2) {
    __shared__ float2 sb[512];
    __shared__ float part[31][8];
    int b = blockIdx.x;
    int tid = threadIdx.x;
    for (int k = tid; k < 512; k += 256)
        sb[k] = inF2[(b * 512 + k) * 127 + 126];
    __syncthreads();
    int ni = tid >> 3, kp = tid & 7;
    if (ni < 31) {
        int n = 961 + 2 * ni;
        float acc = 0.0f;
        for (int k = kp; k < 512; k += 8) {
            float2 x = sb[k];
            float2 t = g_trig[(n * k) % WIN];
            float coef = (k == 0 || k == 511) ? 1.0f : 2.0f;
            acc += coef * (x.x * t.x - x.y * t.y);
        }
        part[ni][kp] = acc;
    }
    __syncthreads();
    if (tid < 31) {
        float s = 0.0f;
#pragma unroll
        for (int q = 0; q < 8; q++) s += part[tid][q];
        g_tail[b * 32 + tid] = s * (1.0f / 1022.0f) * g_synth[961 + 2 * tid];
    }
}

// ---------------- pass 2: overlap-add ----------------
__global__ void k_pass2() {
    int idx = blockIdx.x * blockDim.x + threadIdx.x;
    if (idx >= BATCH * L_OUT) return;
    int b = idx / L_OUT, j = idx - b * L_OUT;
    float v;
    if (j < J_EVEN) {
        int p = 2 * j;
        int t_hi = min(126, p >> 8);
        int t_lo = max(0, p - 766) >> 8;
        float acc = 0.0f;
        for (int t = t_lo; t <= t_hi; t++) {
            int m = j - (t << 7);
            acc += g_frames[(b * 127 + t) * 512 + m];
        }
        v = acc;
    } else {
        int n = j - 15648;
        if (n & 1) v = g_tail[b * 32 + ((n - 961) >> 1)];
        else       v = g_frames[(b * 127 + 126) * 512 + (n >> 1)];
    }
    g_sig[b * SIG_STRIDE + j] = v;
}

// ---------------- transpose: g_sig -> g_sigT[n][f] ----------------
__global__ void k_transpose() {
    __shared__ float tile[32][33];
    int f0 = blockIdx.x * 32;
    int n0 = blockIdx.y * 32;
    int lx = threadIdx.x & 31, ly = threadIdx.x >> 5;
#pragma unroll
    for (int q = 0; q < 4; q++) {
        int fi = ly + q * 8;
        int f = f0 + fi;
        int b = f / 62, t = f - b * 62;
        tile[fi][lx] = g_sig[b * SIG_STRIDE + t * 256 + n0 + lx];
    }
    __syncthreads();
#pragma unroll
    for (int q = 0; q < 4; q++) {
        int ni = ly + q * 8;
        g_sigT[(n0 + ni) * FSTR + f0 + lx] = tile[lx][ni];
    }
}

// ---------------- pass 3: rfft GEMM, 128f x 64k tile, 8x4(complex)/thread ----------------
#define BK3 32
__global__ __launch_bounds__(256, 2) void k_pass3(float2* __restrict__ outF2) {
    __shared__ float Aw[BK3][128], Bc[BK3][64], Bs[BK3][64];
    int tid = threadIdx.x;
    int k0 = blockIdx.x * 64;
    int f0 = blockIdx.y * 128;
    int tx = tid & 15, ty = tid >> 4;

    float pre[16];
#pragma unroll
    for (int r = 0; r < 16; r++) {
        int e = r * 256 + tid;
        pre[r] = g_sigT[(e >> 7) * FSTR + f0 + (e & 127)];
    }

    unsigned long long acc[8][4];
#pragma unroll
    for (int i = 0; i < 8; i++)
#pragma unroll
        for (int j = 0; j < 4; j++) acc[i][j] = 0ULL;

    for (int nc = 0; nc < 1024; nc += BK3) {
#pragma unroll
        for (int r = 0; r < 16; r++) {
            int e = r * 256 + tid;
            Aw[e >> 7][e & 127] = pre[r];
        }
#pragma unroll
        for (int r = 0; r < 2; r++) {
            int e = r * 256 + tid;
            int q = e & 15, nl = e >> 4;
            ((float4*)&Bc[nl][0])[q] = ((const float4*)(g_W3c + (nc + nl) * 512 + k0))[q];
            ((float4*)&Bs[nl][0])[q] = ((const float4*)(g_W3s + (nc + nl) * 512 + k0))[q];
        }
        __syncthreads();
        if (nc + BK3 < 1024) {
#pragma unroll
            for (int r = 0; r < 16; r++) {
                int e = r * 256 + tid;
                pre[r] = g_sigT[(nc + BK3 + (e >> 7)) * FSTR + f0 + (e & 127)];
            }
        }
#pragma unroll 8
        for (int kk = 0; kk < BK3; kk++) {
            float4 aL = ((const float4*)Aw[kk])[ty];
            float4 aH = ((const float4*)Aw[kk])[16 + ty];
            float4 bc4 = ((const float4*)Bc[kk])[tx];
            float4 bs4 = ((const float4*)Bs[kk])[tx];
            unsigned long long b0 = pk2(bc4.x, bs4.x), b1 = pk2(bc4.y, bs4.y);
            unsigned long long b2 = pk2(bc4.z, bs4.z), b3 = pk2(bc4.w, bs4.w);
            float av[8] = {aL.x, aL.y, aL.z, aL.w, aH.x, aH.y, aH.z, aH.w};
#pragma unroll
            for (int i = 0; i < 8; i++) {
                unsigned long long a2 = pk2(av[i], av[i]);
                fma2(acc[i][0], a2, b0);
                fma2(acc[i][1], a2, b1);
                fma2(acc[i][2], a2, b2);
                fma2(acc[i][3], a2, b3);
            }
        }
        __syncthreads();
    }

#pragma unroll
    for (int i = 0; i < 8; i++) {
        int f = f0 + (i < 4 ? ty * 4 + i : 64 + ty * 4 + (i - 4));
        int b = f / 62, t = f - b * 62;
#pragma unroll
        for (int j = 0; j < 4; j++) {
            int k = k0 + tx * 4 + j;
            float2 v = upk(acc[i][j]);
            outF2[(b * 512 + k) * 62 + t] = v;
        }
    }
}

// ---------------- launch ----------------
extern "C" void kernel_launch(void* const* d_in, const int* in_sizes, int n_in,
                              void* d_out, int out_size) {
    (void)in_sizes; (void)n_in; (void)out_size;
    const float2* inF2 = (const float2*)d_in[0];
    float2* outF2 = (float2*)d_out;

    k_setup<<<1, 256>>>();
    k_fill_trig<<<4, 256>>>();
    k_fill_w1<<<512, 256>>>();
    k_fill_w3<<<1024, 256>>>();
    k_pass1<<<dim3(4, 64), 256>>>(inF2);
    k_pass1b<<<64, 256>>>(inF2);
    k_pass2<<<(BATCH * L_OUT + 255) / 256, 256>>>();
    k_transpose<<<dim3(124, 32), 256>>>();
    k_pass3<<<dim3(8, 31), 256>>>(outF2);
}

// round 6
// speedup vs baseline: 2.2389x; 1.6393x over previous
#include <cuda_runtime.h>

#define NBIN 512
#define WIN 1022
#define T_IN 127
#define BATCH 64
#define NF (BATCH * T_IN)       // 8128
#define HOP 256
#define T_OUT 62
#define NF3 (BATCH * T_OUT)     // 3968
#define SIG_STRIDE 16672
#define L_OUT 16670
#define J_EVEN 16608
#define P1STR 8192
#define ZSTR 3968

// ---------------- device scratch ----------------
__device__ float  g_frames[NF * 512];
__device__ float  g_tail[BATCH * 32];
__device__ float  g_sig[BATCH * SIG_STRIDE];
__device__ float  g_P1r[256 * P1STR];        // folded spectrum re plane [k][f]
__device__ float  g_P1i[256 * P1STR];        // folded spectrum im plane [k][f]
__device__ float2 g_zT[512 * ZSTR];          // folded windowed signal (ze,zo) [n][f]
__device__ float  g_W1c[256 * 512];          // folded irfft cos plane, synth folded
__device__ float  g_W1s[256 * 512];          // folded irfft -sin plane, synth folded
__device__ float2 g_W3[512 * 512];           // rfft (cos, -sin) [n][k], n<512
__device__ float2 g_trig[1022];              // (cos(pi j/511), sin(pi j/511))
__device__ float  g_synth[WIN];
__device__ float  g_window[1024];

// ---------------- packed f32x2 helpers ----------------
__device__ __forceinline__ unsigned long long pk2(float lo, float hi) {
    unsigned long long r;
    asm("mov.b64 %0, {%1, %2};" : "=l"(r) : "f"(lo), "f"(hi));
    return r;
}
__device__ __forceinline__ void fma2(unsigned long long& d, unsigned long long a, unsigned long long b) {
    asm("fma.rn.f32x2 %0, %1, %2, %0;" : "+l"(d) : "l"(a), "l"(b));
}
__device__ __forceinline__ float2 upk(unsigned long long v) {
    float2 f;
    asm("mov.b64 {%0, %1}, %2;" : "=f"(f.x), "=f"(f.y) : "l"(v));
    return f;
}

// ---------------- setup ----------------
__global__ void k_setup() {
    __shared__ float sd[256];
    int tid = threadIdx.x;
    double s = 0.0;
    for (int r = 0; r < 4; r++) {
        int i = r * 256 + tid;
        if (i < WIN) {
            double w = 0.5 - 0.5 * cospi(2.0 * (double)i / 1022.0);
            s += w * w;
        }
    }
    sd[tid] = (float)s;
    __syncthreads();
    for (int n = tid; n < 1024; n += 256) {
        if (n < WIN) {
            double w = 0.5 - 0.5 * cospi(2.0 * (double)n / 1022.0);
            g_window[n] = (float)w;
            g_synth[n] = (float)(w / (double)sd[n & 255]);
        } else {
            g_window[n] = 0.0f;
        }
    }
}

__global__ void k_fill_trig() {
    int j = blockIdx.x * blockDim.x + threadIdx.x;
    if (j < 1022) {
        float sn, cs;
        sincospif((float)j / 511.0f, &sn, &cs);
        g_trig[j] = make_float2(cs, sn);
    }
}

// W1 folded: k=0 column holds DC+Nyquist weight; k=1..255 doubled cos/sin
__global__ void k_fill_w1() {
    int k = blockIdx.x;  // 0..255
    const float invN = 1.0f / 1022.0f;
    for (int m = threadIdx.x; m < 512; m += blockDim.x) {
        float vc = 0.0f, vs = 0.0f;
        if (m < 511) {
            float sv = g_synth[2 * m];
            if (k == 0) {
                vc = invN * sv;
            } else {
                int r = (k * m) % 511;
                float2 t = g_trig[2 * r];
                vc = 2.0f * invN * t.x * sv;
                vs = -2.0f * invN * t.y * sv;
            }
        }
        g_W1c[k * 512 + m] = vc;
        g_W1s[k * 512 + m] = vs;
    }
}

// W3 interleaved (cos, -sin), n = 0..511 (folded K); window applied at fold time
__global__ void k_fill_w3() {
    int n = blockIdx.x;  // 0..511
    for (int k = threadIdx.x; k < 512; k += blockDim.x) {
        int j = (n * k) % WIN;
        float2 t = g_trig[j];
        g_W3[n * 512 + k] = make_float2(t.x, -t.y);
    }
}

// ---------------- fold 1: spectrum fold + transpose -> [k][f] planes ----------------
__global__ void k_fold1(const float2* __restrict__ inF2) {
    int f = blockIdx.x * 256 + threadIdx.x;
    int k = blockIdx.y;  // 0..255
    if (f >= NF) return;
    int b = f / 127, t = f - b * 127;
    float2 x0 = inF2[(b * 512 + k) * 127 + t];
    float2 x1 = inF2[(b * 512 + (511 - k)) * 127 + t];
    g_P1r[k * P1STR + f] = x0.x + x1.x;
    g_P1i[k * P1STR + f] = x0.y - x1.y;   // k=0 value unused (W1s[0]=0)
}

// ---------------- pass 1: folded irfft GEMM, 128x128 tile, K=256 ----------------
#define BK1 16
__global__ __launch_bounds__(256, 2) void k_pass1() {
    __shared__ float Ar[BK1][128], Ai[BK1][128], Bc[BK1][128], Bs[BK1][128];
    int tid = threadIdx.x;
    int m0 = blockIdx.x * 128;
    int f0 = blockIdx.y * 128;
    int tx = tid & 15, ty = tid >> 4;

    float4 preR[2], preI[2];
#pragma unroll
    for (int r = 0; r < 2; r++) {
        int e = r * 256 + tid;
        int q = e & 31, kl = e >> 5;
        preR[r] = ((const float4*)(g_P1r + kl * P1STR + f0))[q];
        preI[r] = ((const float4*)(g_P1i + kl * P1STR + f0))[q];
    }

    unsigned long long acc[8][4];
#pragma unroll
    for (int i = 0; i < 8; i++)
#pragma unroll
        for (int j = 0; j < 4; j++) acc[i][j] = 0ULL;

    for (int kc = 0; kc < 256; kc += BK1) {
#pragma unroll
        for (int r = 0; r < 2; r++) {
            int e = r * 256 + tid;
            int q = e & 31, kl = e >> 5;
            ((float4*)&Ar[kl][0])[q] = preR[r];
            ((float4*)&Ai[kl][0])[q] = preI[r];
            ((float4*)&Bc[kl][0])[q] = ((const float4*)(g_W1c + (kc + kl) * 512 + m0))[q];
            ((float4*)&Bs[kl][0])[q] = ((const float4*)(g_W1s + (kc + kl) * 512 + m0))[q];
        }
        __syncthreads();
        if (kc + BK1 < 256) {
#pragma unroll
            for (int r = 0; r < 2; r++) {
                int e = r * 256 + tid;
                int q = e & 31, kl = e >> 5;
                preR[r] = ((const float4*)(g_P1r + (kc + BK1 + kl) * P1STR + f0))[q];
                preI[r] = ((const float4*)(g_P1i + (kc + BK1 + kl) * P1STR + f0))[q];
            }
        }
#pragma unroll 8
        for (int kk = 0; kk < BK1; kk++) {
            float4 arL = ((const float4*)Ar[kk])[ty];
            float4 arH = ((const float4*)Ar[kk])[16 + ty];
            float4 aiL = ((const float4*)Ai[kk])[ty];
            float4 aiH = ((const float4*)Ai[kk])[16 + ty];
            float4 bcL = ((const float4*)Bc[kk])[tx];
            float4 bcH = ((const float4*)Bc[kk])[16 + tx];
            float4 bsL = ((const float4*)Bs[kk])[tx];
            float4 bsH = ((const float4*)Bs[kk])[16 + tx];
            unsigned long long bc0 = pk2(bcL.x, bcL.y), bc1 = pk2(bcL.z, bcL.w);
            unsigned long long bc2 = pk2(bcH.x, bcH.y), bc3 = pk2(bcH.z, bcH.w);
            unsigned long long bs0 = pk2(bsL.x, bsL.y), bs1 = pk2(bsL.z, bsL.w);
            unsigned long long bs2 = pk2(bsH.x, bsH.y), bs3 = pk2(bsH.z, bsH.w);
            float arv[8] = {arL.x, arL.y, arL.z, arL.w, arH.x, arH.y, arH.z, arH.w};
            float aiv[8] = {aiL.x, aiL.y, aiL.z, aiL.w, aiH.x, aiH.y, aiH.z, aiH.w};
#pragma unroll
            for (int i = 0; i < 8; i++) {
                unsigned long long ar2 = pk2(arv[i], arv[i]);
                unsigned long long ai2 = pk2(aiv[i], aiv[i]);
                fma2(acc[i][0], ar2, bc0); fma2(acc[i][0], ai2, bs0);
                fma2(acc[i][1], ar2, bc1); fma2(acc[i][1], ai2, bs1);
                fma2(acc[i][2], ar2, bc2); fma2(acc[i][2], ai2, bs2);
                fma2(acc[i][3], ar2, bc3); fma2(acc[i][3], ai2, bs3);
            }
        }
        __syncthreads();
    }

#pragma unroll
    for (int i = 0; i < 8; i++) {
        int f = f0 + (i < 4 ? ty * 4 + i : 64 + ty * 4 + (i - 4));
        if (f < NF) {
#pragma unroll
            for (int jj = 0; jj < 4; jj++) {
                int m = (jj < 2) ? (m0 + tx * 4 + 2 * jj) : (m0 + 64 + tx * 4 + 2 * (jj - 2));
                float2 v = upk(acc[i][jj]);
                g_frames[f * 512 + m] = v.x;      // synth folded in W1
                g_frames[f * 512 + m + 1] = v.y;  // m=511 col is zero plane
            }
        }
    }
}

// ---------------- pass 1b: odd tail of frame 126 (LUT) ----------------
__global__ void k_pass1b(const float2* __restrict__ inF2) {
    __shared__ float2 sb[512];
    __shared__ float part[31][8];
    int b = blockIdx.x;
    int tid = threadIdx.x;
    for (int k = tid; k < 512; k += 256)
        sb[k] = inF2[(b * 512 + k) * 127 + 126];
    __syncthreads();
    int ni = tid >> 3, kp = tid & 7;
    if (ni < 31) {
        int n = 961 + 2 * ni;
        float acc = 0.0f;
        for (int k = kp; k < 512; k += 8) {
            float2 x = sb[k];
            float2 t = g_trig[(n * k) % WIN];
            float coef = (k == 0 || k == 511) ? 1.0f : 2.0f;
            acc += coef * (x.x * t.x - x.y * t.y);
        }
        part[ni][kp] = acc;
    }
    __syncthreads();
    if (tid < 31) {
        float s = 0.0f;
#pragma unroll
        for (int q = 0; q < 8; q++) s += part[tid][q];
        g_tail[b * 32 + tid] = s * (1.0f / 1022.0f) * g_synth[961 + 2 * tid];
    }
}

// ---------------- pass 2: overlap-add ----------------
__global__ void k_pass2() {
    int idx = blockIdx.x * blockDim.x + threadIdx.x;
    if (idx >= BATCH * L_OUT) return;
    int b = idx / L_OUT, j = idx - b * L_OUT;
    float v;
    if (j < J_EVEN) {
        int p = 2 * j;
        int t_hi = min(126, p >> 8);
        int t_lo = max(0, p - 766) >> 8;
        float acc = 0.0f;
        for (int t = t_lo; t <= t_hi; t++) {
            int m = j - (t << 7);
            acc += g_frames[(b * 127 + t) * 512 + m];
        }
        v = acc;
    } else {
        int n = j - 15648;
        if (n & 1) v = g_tail[b * 32 + ((n - 961) >> 1)];
        else       v = g_frames[(b * 127 + 126) * 512 + (n >> 1)];
    }
    g_sig[b * SIG_STRIDE + j] = v;
}

// ---------------- fold 3: window + symmetry fold + transpose -> (ze,zo)[n][f] ----------------
__global__ void k_fold3() {
    __shared__ float2 tile[32][33];
    int f0 = blockIdx.x * 32;
    int n0 = blockIdx.y * 32;
    int lx = threadIdx.x & 31, ly = threadIdx.x >> 5;
#pragma unroll
    for (int q = 0; q < 4; q++) {
        int fi = ly + q * 8;
        int f = f0 + fi;
        int b = f / 62, t = f - b * 62;
        int base = b * SIG_STRIDE + t * 256;
        int n = n0 + lx;
        float y = g_sig[base + n];
        float yp = (n >= 1 && n <= 510) ? g_sig[base + 1022 - n] : 0.0f;
        float w = g_window[n];
        tile[fi][lx] = make_float2(w * (y + yp), w * (y - yp));
    }
    __syncthreads();
#pragma unroll
    for (int q = 0; q < 4; q++) {
        int ni = ly + q * 8;
        g_zT[(n0 + ni) * ZSTR + f0 + lx] = tile[lx][ni];
    }
}

// ---------------- pass 3: folded rfft GEMM, 128f x 64k tile, K=512 ----------------
#define BK3 32
__global__ __launch_bounds__(256, 2) void k_pass3(float2* __restrict__ outF2) {
    __shared__ float2 Ap[BK3][128];   // (ze, zo)
    __shared__ float2 Bp[BK3][64];    // (cos, -sin)
    int tid = threadIdx.x;
    int k0 = blockIdx.x * 64;
    int f0 = blockIdx.y * 128;
    int tx = tid & 15, ty = tid >> 4;

    float4 preA[8];
#pragma unroll
    for (int r = 0; r < 8; r++) {
        int e = r * 256 + tid;
        int q = e & 63, nl = e >> 6;
        preA[r] = ((const float4*)(g_zT + nl * ZSTR + f0))[q];
    }

    unsigned long long acc[8][4];
#pragma unroll
    for (int i = 0; i < 8; i++)
#pragma unroll
        for (int j = 0; j < 4; j++) acc[i][j] = 0ULL;

    for (int nc = 0; nc < 512; nc += BK3) {
#pragma unroll
        for (int r = 0; r < 8; r++) {
            int e = r * 256 + tid;
            int q = e & 63, nl = e >> 6;
            ((float4*)&Ap[nl][0])[q] = preA[r];
        }
        // B tile: 32 rows x 64 float2 = 32 float4 per row = 1024 float4 total
#pragma unroll
        for (int r = 0; r < 4; r++) {
            int e = r * 256 + tid;
            int q = e & 31, nl = e >> 5;
            ((float4*)&Bp[nl][0])[q] = ((const float4*)(g_W3 + (nc + nl) * 512 + k0))[q];
        }
        __syncthreads();
        if (nc + BK3 < 512) {
#pragma unroll
            for (int r = 0; r < 8; r++) {
                int e = r * 256 + tid;
                int q = e & 63, nl = e >> 6;
                preA[r] = ((const float4*)(g_zT + (nc + BK3 + nl) * ZSTR + f0))[q];
            }
        }
#pragma unroll 8
        for (int kk = 0; kk < BK3; kk++) {
            ulonglong2 aL0 = ((const ulonglong2*)&Ap[kk][0])[ty * 2];
            ulonglong2 aL1 = ((const ulonglong2*)&Ap[kk][0])[ty * 2 + 1];
            ulonglong2 aH0 = ((const ulonglong2*)&Ap[kk][0])[32 + ty * 2];
            ulonglong2 aH1 = ((const ulonglong2*)&Ap[kk][0])[32 + ty * 2 + 1];
            ulonglong2 b01 = ((const ulonglong2*)&Bp[kk][0])[tx * 2];
            ulonglong2 b23 = ((const ulonglong2*)&Bp[kk][0])[tx * 2 + 1];
            unsigned long long av[8] = {aL0.x, aL0.y, aL1.x, aL1.y, aH0.x, aH0.y, aH1.x, aH1.y};
            unsigned long long bv[4] = {b01.x, b01.y, b23.x, b23.y};
#pragma unroll
            for (int i = 0; i < 8; i++) {
#pragma unroll
                for (int j = 0; j < 4; j++) {
                    fma2(acc[i][j], av[i], bv[j]);   // lo: re += ze*cos ; hi: im += zo*(-sin)
                }
            }
        }
        __syncthreads();
    }

#pragma unroll
    for (int i = 0; i < 8; i++) {
        int f = f0 + (i < 4 ? ty * 4 + i : 64 + ty * 4 + (i - 4));
        int b = f / 62, t = f - b * 62;
#pragma unroll
        for (int j = 0; j < 4; j++) {
            int k = k0 + tx * 4 + j;
            float2 v = upk(acc[i][j]);
            outF2[(b * 512 + k) * 62 + t] = v;
        }
    }
}

// ---------------- launch ----------------
extern "C" void kernel_launch(void* const* d_in, const int* in_sizes, int n_in,
                              void* d_out, int out_size) {
    (void)in_sizes; (void)n_in; (void)out_size;
    const float2* inF2 = (const float2*)d_in[0];
    float2* outF2 = (float2*)d_out;

    k_setup<<<1, 256>>>();
    k_fill_trig<<<4, 256>>>();
    k_fill_w1<<<256, 256>>>();
    k_fill_w3<<<512, 256>>>();
    k_fold1<<<dim3(32, 256), 256>>>(inF2);
    k_pass1<<<dim3(4, 64), 256>>>();
    k_pass1b<<<64, 256>>>(inF2);
    k_pass2<<<(BATCH * L_OUT + 255) / 256, 256>>>();
    k_fold3<<<dim3(124, 16), 256>>>();
    k_pass3<<<dim3(8, 31), 256>>>(outF2);
}

// round 8
// speedup vs baseline: 2.4726x; 1.1044x over previous
#include <cuda_runtime.h>
#include <cuda_bf16.h>
#include <cstdint>

#define WIN 1022
#define T_IN 127
#define BATCH 64
#define NF (BATCH * T_IN)       // 8128
#define HOP 256
#define T_OUT 62
#define NF3 (BATCH * T_OUT)     // 3968
#define SIG_STRIDE 16672
#define L_OUT 16670
#define J_EVEN 16608

#define BLOB 16384              // one 128row x 64col bf16 SW128 tile
#define NCH1 24                 // pass1 K-chunks (3-term split, 2 planes, K=256)
#define NCH3 48                 // pass3 K-chunks (2 chains x 24)

// ---------------- device scratch ----------------
__device__ float  g_frames[NF * 512];
__device__ float  g_tail[BATCH * 32];
__device__ float  g_sig[BATCH * SIG_STRIDE];
__device__ float2 g_trig[1022];
__device__ float  g_synth[WIN];
__device__ float  g_window[1024];
__device__ __align__(16) char g_A1cat[64 * NCH1 * BLOB];   // ~25MB
__device__ __align__(16) char g_B1cat[4 * NCH1 * BLOB];    // 1.5MB
__device__ __align__(16) char g_A3cat[31 * NCH3 * BLOB];   // ~24MB
__device__ __align__(16) char g_B3cat[4 * NCH3 * BLOB];    // 3MB

// ---------------- helpers ----------------
__device__ __forceinline__ uint32_t smem_to_u32(const void* p) {
    uint32_t a;
    asm("{ .reg .u64 t; cvta.to.shared.u64 t, %1; cvt.u32.u64 %0, t; }" : "=r"(a) : "l"(p));
    return a;
}
__device__ __forceinline__ void cp16(uint32_t saddr, const void* gaddr) {
    asm volatile("cp.async.cg.shared.global [%0], [%1], 16;" :: "r"(saddr), "l"(gaddr));
}
#define CP_COMMIT() asm volatile("cp.async.commit_group;" ::: "memory")
#define CP_WAIT(n)  asm volatile("cp.async.wait_group %0;" :: "n"(n) : "memory")

__device__ __forceinline__ void ldsm_x4(uint32_t& r0, uint32_t& r1, uint32_t& r2, uint32_t& r3, uint32_t addr) {
    asm volatile("ldmatrix.sync.aligned.m8n8.x4.shared.b16 {%0,%1,%2,%3}, [%4];"
                 : "=r"(r0), "=r"(r1), "=r"(r2), "=r"(r3) : "r"(addr));
}
__device__ __forceinline__ void mma16816(float* d, const uint32_t* a, uint32_t b0, uint32_t b1) {
    asm volatile("mma.sync.aligned.m16n8k16.row.col.f32.bf16.bf16.f32 "
                 "{%0,%1,%2,%3},{%4,%5,%6,%7},{%8,%9},{%0,%1,%2,%3};"
                 : "+f"(d[0]), "+f"(d[1]), "+f"(d[2]), "+f"(d[3])
                 : "r"(a[0]), "r"(a[1]), "r"(a[2]), "r"(a[3]), "r"(b0), "r"(b1));
}
__device__ __forceinline__ unsigned short bfb(float x) {
    __nv_bfloat16 h = __float2bfloat16_rn(x);
    return *reinterpret_cast<unsigned short*>(&h);
}
__device__ __forceinline__ void split_bf(float x, unsigned short& hi, unsigned short& lo) {
    __nv_bfloat16 h = __float2bfloat16_rn(x);
    hi = *reinterpret_cast<unsigned short*>(&h);
    lo = bfb(x - __bfloat162float(h));
}
__device__ __forceinline__ int swz(int row, int col) {  // byte offset in blob, col in bf16 units (<64)
    int b = row * 128 + col * 2;
    return b ^ ((b >> 3) & 0x70);
}

// ---------------- setup ----------------
__global__ void k_setup() {
    __shared__ float sd[256];
    int tid = threadIdx.x;
    double s = 0.0;
    for (int r = 0; r < 4; r++) {
        int i = r * 256 + tid;
        if (i < WIN) { double w = 0.5 - 0.5 * cospi(2.0 * (double)i / 1022.0); s += w * w; }
    }
    sd[tid] = (float)s;
    __syncthreads();
    for (int n = tid; n < 1024; n += 256) {
        if (n < WIN) {
            double w = 0.5 - 0.5 * cospi(2.0 * (double)n / 1022.0);
            g_window[n] = (float)w;
            g_synth[n] = (float)(w / (double)sd[n & 255]);
        } else g_window[n] = 0.0f;
    }
}

__global__ void k_fill_trig() {
    int j = blockIdx.x * blockDim.x + threadIdx.x;
    if (j < 1022) {
        float sn, cs;
        sincospif((float)j / 511.0f, &sn, &cs);
        g_trig[j] = make_float2(cs, sn);
    }
}

// ---------------- B1: folded irfft weights, split, blobbed ----------------
// chunk seq: 0-3 Bc_hi | 4-7 Bs_hi | 8-11 Bc_hi | 12-15 Bs_hi | 16-19 Bc_lo | 20-23 Bs_lo
__global__ void k_fill_w1() {
    int m = blockIdx.x;          // 0..511
    int k = threadIdx.x;         // 0..255
    const float invN = 1.0f / 1022.0f;
    float vc = 0.0f, vs = 0.0f;
    if (m < 511) {
        float sv = g_synth[2 * m];
        if (k == 0) vc = invN * sv;
        else {
            int r = (k * m) % 511;
            float2 t = g_trig[2 * r];
            vc = 2.0f * invN * t.x * sv;
            vs = -2.0f * invN * t.y * sv;
        }
    }
    unsigned short ch, cl, sh, sl;
    split_bf(vc, ch, cl);
    split_bf(vs, sh, sl);
    char* base = g_B1cat + (size_t)(m >> 7) * NCH1 * BLOB;
    int chunk = k >> 6, off = swz(m & 127, k & 63);
    *(unsigned short*)(base + (chunk) * BLOB + off) = ch;
    *(unsigned short*)(base + (8 + chunk) * BLOB + off) = ch;
    *(unsigned short*)(base + (4 + chunk) * BLOB + off) = sh;
    *(unsigned short*)(base + (12 + chunk) * BLOB + off) = sh;
    *(unsigned short*)(base + (16 + chunk) * BLOB + off) = cl;
    *(unsigned short*)(base + (20 + chunk) * BLOB + off) = sl;
}

// ---------------- B3: rfft weights, split, blobbed ----------------
// re chain (0-23): 0-7 Wc_hi | 8-15 Wc_hi | 16-23 Wc_lo
// im chain (24-47): 24-31 Ws_hi | 32-39 Ws_hi | 40-47 Ws_lo
__global__ void k_fill_w3() {
    int kb = blockIdx.x;         // 0..511
    char* base = g_B3cat + (size_t)(kb >> 7) * NCH3 * BLOB;
    int row = kb & 127;
    for (int n = threadIdx.x; n < 512; n += 256) {
        int j = (n * kb) % WIN;
        float2 t = g_trig[j];
        unsigned short ch, cl, sh, sl;
        split_bf(t.x, ch, cl);
        split_bf(-t.y, sh, sl);
        int chunk = n >> 6, off = swz(row, n & 63);
        *(unsigned short*)(base + (chunk) * BLOB + off) = ch;
        *(unsigned short*)(base + (8 + chunk) * BLOB + off) = ch;
        *(unsigned short*)(base + (16 + chunk) * BLOB + off) = cl;
        *(unsigned short*)(base + (24 + chunk) * BLOB + off) = sh;
        *(unsigned short*)(base + (32 + chunk) * BLOB + off) = sh;
        *(unsigned short*)(base + (40 + chunk) * BLOB + off) = sl;
    }
}

// ---------------- fold1: spectrum fold, split, blobbed A ----------------
// chunk seq: 0-3 Ar_hi | 4-7 Ai_hi | 8-11 Ar_lo | 12-15 Ai_lo | 16-19 Ar_hi | 20-23 Ai_hi
__global__ void k_fold1(const float2* __restrict__ inF2) {
    __shared__ ushort4 tile[32][33];
    int f0 = blockIdx.x * 32;    // 0..8096
    int k0 = blockIdx.y * 32;    // 0..224
    int lx = threadIdx.x & 31, ly = threadIdx.x >> 5;
    int f = f0 + lx;
    int b = f / 127, t = f - b * 127;
#pragma unroll
    for (int q = 0; q < 4; q++) {
        int k = k0 + ly + 8 * q;
        float2 x0 = inF2[(b * 512 + k) * 127 + t];
        float2 x1 = inF2[(b * 512 + 511 - k) * 127 + t];
        float xr = x0.x + x1.x, xi = x0.y - x1.y;
        ushort4 v;
        split_bf(xr, v.x, v.z);
        split_bf(xi, v.y, v.w);
        tile[ly + 8 * q][lx] = v;
    }
    __syncthreads();
    char* base = g_A1cat + (size_t)(f0 >> 7) * NCH1 * BLOB;
    int row0 = f0 & 127;
    int kk = k0 + lx;
    int chunk = kk >> 6, col = kk & 63;
#pragma unroll
    for (int q = 0; q < 4; q++) {
        int fl = ly + 8 * q;
        ushort4 v = tile[lx][fl];
        int off = swz(row0 + fl, col);
        *(unsigned short*)(base + (chunk) * BLOB + off) = v.x;
        *(unsigned short*)(base + (16 + chunk) * BLOB + off) = v.x;
        *(unsigned short*)(base + (4 + chunk) * BLOB + off) = v.y;
        *(unsigned short*)(base + (20 + chunk) * BLOB + off) = v.y;
        *(unsigned short*)(base + (8 + chunk) * BLOB + off) = v.z;
        *(unsigned short*)(base + (12 + chunk) * BLOB + off) = v.w;
    }
}

// ---------------- GEMM 1: frames[f][m] = A1 @ B1^T via mma.sync ----------------
__global__ void __launch_bounds__(256) k_mma1() {
    extern __shared__ char smem[];
    uint32_t sb = smem_to_u32(smem);
    int tid = threadIdx.x, lane = tid & 31, wid = tid >> 5;
    int wm = wid >> 2, wn = wid & 3;
    int ntile = blockIdx.x;      // m tile 0..3
    int ftile = blockIdx.y;      // f tile 0..63
    const char* Ab = g_A1cat + (size_t)ftile * NCH1 * BLOB;
    const char* Bb = g_B1cat + (size_t)ntile * NCH1 * BLOB;

    float acc[4][4][4];
#pragma unroll
    for (int i = 0; i < 4; i++)
#pragma unroll
        for (int j = 0; j < 4; j++)
#pragma unroll
            for (int e = 0; e < 4; e++) acc[i][j][e] = 0.0f;

    // stage chunk 0 into buf 0
    {
        uint32_t da = sb, db = sb + BLOB;
#pragma unroll
        for (int r = 0; r < 4; r++) {
            int e = tid + 256 * r;
            cp16(da + e * 16, Ab + e * 16);
            cp16(db + e * 16, Bb + e * 16);
        }
        CP_COMMIT();
    }
    for (int c = 0; c < NCH1; c++) {
        int buf = c & 1;
        if (c + 1 < NCH1) {
            int nb = (c + 1) & 1;
            uint32_t da = sb + nb * 2 * BLOB, db = da + BLOB;
            const char* ga = Ab + (size_t)(c + 1) * BLOB;
            const char* gb = Bb + (size_t)(c + 1) * BLOB;
#pragma unroll
            for (int r = 0; r < 4; r++) {
                int e = tid + 256 * r;
                cp16(da + e * 16, ga + e * 16);
                cp16(db + e * 16, gb + e * 16);
            }
            CP_COMMIT();
            CP_WAIT(1);
        } else {
            CP_WAIT(0);
        }
        __syncthreads();
        uint32_t SA = sb + buf * 2 * BLOB, SB = SA + BLOB;
#pragma unroll
        for (int k0 = 0; k0 < 64; k0 += 16) {
            uint32_t af[4][4], bf[2][4];
            int colu = k0 + ((lane >> 4) << 3);
#pragma unroll
            for (int i = 0; i < 4; i++) {
                int row = wm * 64 + i * 16 + (lane & 15);
                ldsm_x4(af[i][0], af[i][1], af[i][2], af[i][3], SA + swz(row, colu));
            }
#pragma unroll
            for (int j2 = 0; j2 < 2; j2++) {
                int row = wn * 32 + j2 * 16 + (lane & 15);
                ldsm_x4(bf[j2][0], bf[j2][1], bf[j2][2], bf[j2][3], SB + swz(row, colu));
            }
#pragma unroll
            for (int i = 0; i < 4; i++)
#pragma unroll
                for (int j = 0; j < 4; j++)
                    mma16816(acc[i][j], af[i], bf[j >> 1][j & 1], bf[j >> 1][(j & 1) + 2]);
        }
        __syncthreads();
    }
    // epilogue: D[f][m]
    int g = lane >> 2, t4 = lane & 3;
#pragma unroll
    for (int i = 0; i < 4; i++) {
        int f0 = ftile * 128 + wm * 64 + i * 16 + g;
#pragma unroll
        for (int j = 0; j < 4; j++) {
            int col = ntile * 128 + wn * 32 + j * 8 + t4 * 2;
            if (f0 < NF)
                *(float2*)(g_frames + (size_t)f0 * 512 + col) = make_float2(acc[i][j][0], acc[i][j][1]);
            if (f0 + 8 < NF)
                *(float2*)(g_frames + (size_t)(f0 + 8) * 512 + col) = make_float2(acc[i][j][2], acc[i][j][3]);
        }
    }
}

// ---------------- pass 1b: odd tail of frame 126 (LUT) ----------------
__global__ void k_pass1b(const float2* __restrict__ inF2) {
    __shared__ float2 sbuf[512];
    __shared__ float part[31][8];
    int b = blockIdx.x;
    int tid = threadIdx.x;
    for (int k = tid; k < 512; k += 256)
        sbuf[k] = inF2[(b * 512 + k) * 127 + 126];
    __syncthreads();
    int ni = tid >> 3, kp = tid & 7;
    if (ni < 31) {
        int n = 961 + 2 * ni;
        float acc = 0.0f;
        for (int k = kp; k < 512; k += 8) {
            float2 x = sbuf[k];
            float2 t = g_trig[(n * k) % WIN];
            float coef = (k == 0 || k == 511) ? 1.0f : 2.0f;
            acc += coef * (x.x * t.x - x.y * t.y);
        }
        part[ni][kp] = acc;
    }
    __syncthreads();
    if (tid < 31) {
        float s = 0.0f;
#pragma unroll
        for (int q = 0; q < 8; q++) s += part[tid][q];
        g_tail[b * 32 + tid] = s * (1.0f / 1022.0f) * g_synth[961 + 2 * tid];
    }
}

// ---------------- pass 2: overlap-add ----------------
__global__ void k_pass2() {
    int idx = blockIdx.x * blockDim.x + threadIdx.x;
    if (idx >= BATCH * L_OUT) return;
    int b = idx / L_OUT, j = idx - b * L_OUT;
    float v;
    if (j < J_EVEN) {
        int p = 2 * j;
        int t_hi = min(126, p >> 8);
        int t_lo = max(0, p - 766) >> 8;
        float acc = 0.0f;
        for (int t = t_lo; t <= t_hi; t++) {
            int m = j - (t << 7);
            acc += g_frames[(b * 127 + t) * 512 + m];
        }
        v = acc;
    } else {
        int n = j - 15648;
        if (n & 1) v = g_tail[b * 32 + ((n - 961) >> 1)];
        else       v = g_frames[(b * 127 + 126) * 512 + (n >> 1)];
    }
    g_sig[b * SIG_STRIDE + j] = v;
}

// ---------------- fold3: window + symmetry fold, split, blobbed ----------------
// A chunks (z): 0-7 ze_hi | 8-15 ze_lo | 16-23 ze_hi | 24-31 zo_hi | 32-39 zo_lo | 40-47 zo_hi
__global__ void k_fold3() {
    __shared__ ushort4 tile[32][33];
    int f0 = blockIdx.x * 32;    // 0..3936
    int n0 = blockIdx.y * 32;    // 0..480
    int lx = threadIdx.x & 31, ly = threadIdx.x >> 5;
    int f = f0 + lx;
    int b = f / 62, t = f - b * 62;
    int bs = b * SIG_STRIDE + t * 256;
#pragma unroll
    for (int q = 0; q < 4; q++) {
        int n = n0 + ly + 8 * q;
        float y = g_sig[bs + n];
        float yp = (n >= 1 && n <= 510) ? g_sig[bs + 1022 - n] : 0.0f;
        float w = g_window[n];
        ushort4 v;
        split_bf(w * (y + yp), v.x, v.y);
        split_bf(w * (y - yp), v.z, v.w);
        tile[ly + 8 * q][lx] = v;
    }
    __syncthreads();
    char* base = g_A3cat + (size_t)(f0 >> 7) * NCH3 * BLOB;
    int row0 = f0 & 127;
    int nn = n0 + lx;
    int chunk = nn >> 6, col = nn & 63;
#pragma unroll
    for (int q = 0; q < 4; q++) {
        int fl = ly + 8 * q;
        ushort4 v = tile[lx][fl];
        int off = swz(row0 + fl, col);
        *(unsigned short*)(base + (chunk) * BLOB + off) = v.x;
        *(unsigned short*)(base + (16 + chunk) * BLOB + off) = v.x;
        *(unsigned short*)(base + (8 + chunk) * BLOB + off) = v.y;
        *(unsigned short*)(base + (24 + chunk) * BLOB + off) = v.z;
        *(unsigned short*)(base + (40 + chunk) * BLOB + off) = v.z;
        *(unsigned short*)(base + (32 + chunk) * BLOB + off) = v.w;
    }
}

// ---------------- GEMM 3: S[k][f] re+im via mma.sync (M=k from W3, N=f from z) ----------------
__global__ void __launch_bounds__(256) k_mma3(float2* __restrict__ outF2) {
    extern __shared__ char smem[];
    uint32_t sb = smem_to_u32(smem);
    int tid = threadIdx.x, lane = tid & 31, wid = tid >> 5;
    int wm = wid >> 2, wn = wid & 3;
    int ftile = blockIdx.x;      // f tile 0..30
    int ktile = blockIdx.y;      // k tile 0..3
    const char* Ab = g_B3cat + (size_t)ktile * NCH3 * BLOB;   // M operand = W3 (k rows)
    const char* Bb = g_A3cat + (size_t)ftile * NCH3 * BLOB;   // N operand = z (f rows)

    float acc[4][4][4], sv[4][4][4];
#pragma unroll
    for (int i = 0; i < 4; i++)
#pragma unroll
        for (int j = 0; j < 4; j++)
#pragma unroll
            for (int e = 0; e < 4; e++) acc[i][j][e] = 0.0f;

    {
        uint32_t da = sb, db = sb + BLOB;
#pragma unroll
        for (int r = 0; r < 4; r++) {
            int e = tid + 256 * r;
            cp16(da + e * 16, Ab + e * 16);
            cp16(db + e * 16, Bb + e * 16);
        }
        CP_COMMIT();
    }
    for (int c = 0; c < NCH3; c++) {
        int buf = c & 1;
        if (c + 1 < NCH3) {
            int nb = (c + 1) & 1;
            uint32_t da = sb + nb * 2 * BLOB, db = da + BLOB;
            const char* ga = Ab + (size_t)(c + 1) * BLOB;
            const char* gb = Bb + (size_t)(c + 1) * BLOB;
#pragma unroll
            for (int r = 0; r < 4; r++) {
                int e = tid + 256 * r;
                cp16(da + e * 16, ga + e * 16);
                cp16(db + e * 16, gb + e * 16);
            }
            CP_COMMIT();
            CP_WAIT(1);
        } else {
            CP_WAIT(0);
        }
        __syncthreads();
        uint32_t SA = sb + buf * 2 * BLOB, SB = SA + BLOB;
#pragma unroll
        for (int k0 = 0; k0 < 64; k0 += 16) {
            uint32_t af[4][4], bf[2][4];
            int colu = k0 + ((lane >> 4) << 3);
#pragma unroll
            for (int i = 0; i < 4; i++) {
                int row = wm * 64 + i * 16 + (lane & 15);
                ldsm_x4(af[i][0], af[i][1], af[i][2], af[i][3], SA + swz(row, colu));
            }
#pragma unroll
            for (int j2 = 0; j2 < 2; j2++) {
                int row = wn * 32 + j2 * 16 + (lane & 15);
                ldsm_x4(bf[j2][0], bf[j2][1], bf[j2][2], bf[j2][3], SB + swz(row, colu));
            }
#pragma unroll
            for (int i = 0; i < 4; i++)
#pragma unroll
                for (int j = 0; j < 4; j++)
                    mma16816(acc[i][j], af[i], bf[j >> 1][j & 1], bf[j >> 1][(j & 1) + 2]);
        }
        __syncthreads();
        if (c == 23) {   // end of re chain: save and reset
#pragma unroll
            for (int i = 0; i < 4; i++)
#pragma unroll
                for (int j = 0; j < 4; j++)
#pragma unroll
                    for (int e = 0; e < 4; e++) { sv[i][j][e] = acc[i][j][e]; acc[i][j][e] = 0.0f; }
        }
    }
    // epilogue: rows = k bins, cols = frames f; out (re=sv, im=acc)
    int g = lane >> 2, t4 = lane & 3;
#pragma unroll
    for (int i = 0; i < 4; i++) {
        int kb = ktile * 128 + wm * 64 + i * 16 + g;
#pragma unroll
        for (int j = 0; j < 4; j++) {
            int fc = ftile * 128 + wn * 32 + j * 8 + t4 * 2;
            int b0 = fc / 62, t0 = fc - b0 * 62;
            int b1 = (fc + 1) / 62, t1 = fc + 1 - b1 * 62;
            outF2[((size_t)b0 * 512 + kb) * 62 + t0] = make_float2(sv[i][j][0], acc[i][j][0]);
            outF2[((size_t)b1 * 512 + kb) * 62 + t1] = make_float2(sv[i][j][1], acc[i][j][1]);
            outF2[((size_t)b0 * 512 + kb + 8) * 62 + t0] = make_float2(sv[i][j][2], acc[i][j][2]);
            outF2[((size_t)b1 * 512 + kb + 8) * 62 + t1] = make_float2(sv[i][j][3], acc[i][j][3]);
        }
    }
}

// ---------------- launch ----------------
extern "C" void kernel_launch(void* const* d_in, const int* in_sizes, int n_in,
                              void* d_out, int out_size) {
    (void)in_sizes; (void)n_in; (void)out_size;
    const float2* inF2 = (const float2*)d_in[0];
    float2* outF2 = (float2*)d_out;

    cudaFuncSetAttribute(k_mma1, cudaFuncAttributeMaxDynamicSharedMemorySize, 4 * BLOB);
    cudaFuncSetAttribute(k_mma3, cudaFuncAttributeMaxDynamicSharedMemorySize, 4 * BLOB);

    k_setup<<<1, 256>>>();
    k_fill_trig<<<4, 256>>>();
    k_fill_w1<<<512, 256>>>();
    k_fill_w3<<<512, 256>>>();
    k_fold1<<<dim3(254, 8), 256>>>(inF2);
    k_mma1<<<dim3(4, 64), 256, 4 * BLOB>>>();
    k_pass1b<<<64, 256>>>(inF2);
    k_pass2<<<(BATCH * L_OUT + 255) / 256, 256>>>();
    k_fold3<<<dim3(124, 16), 256>>>();
    k_mma3<<<dim3(31, 4), 256, 4 * BLOB>>>(outF2);
}

// round 9
// speedup vs baseline: 3.7300x; 1.5085x over previous
#include <cuda_runtime.h>
#include <cuda_bf16.h>
#include <cstdint>

#define WIN 1022
#define T_IN 127
#define BATCH 64
#define NF (BATCH * T_IN)       // 8128
#define HOP 256
#define T_OUT 62
#define NF3 (BATCH * T_OUT)     // 3968
#define SIG_STRIDE 16672
#define L_OUT 16670
#define J_EVEN 16608

#define BLOB 16384              // one 128row x 64col bf16 SW128 tile
#define NCH1 24                 // pass1 schedule steps
#define NCH3 48                 // pass3 schedule steps (re 0-23, im 24-47)
#define CH1_BYTES 32768         // A 16K + B 16K
#define CH3_BYTES 24576         // A 16K + B 8K

// ---------------- device scratch ----------------
__device__ float  g_frames[NF * 512];
__device__ float  g_tail[BATCH * 32];
__device__ float  g_sig[BATCH * SIG_STRIDE];
__device__ float2 g_trig[1022];
__device__ float  g_synth[WIN];
__device__ float  g_window[1024];
__device__ __align__(16) char g_A1cat[64 * 16 * BLOB];   // 16MB: 0-3 Arh | 4-7 Aih | 8-11 Arl | 12-15 Ail
__device__ __align__(16) char g_B1cat[4 * 16 * BLOB];    // 1MB:  0-3 Bch | 4-7 Bsh | 8-11 Bcl | 12-15 Bsl
__device__ __align__(16) char g_A3cat[31 * 32 * BLOB];   // 16MB: 0-7 zeh | 8-15 zel | 16-23 zoh | 24-31 zol
__device__ __align__(16) char g_B3cat[4 * 32 * BLOB];    // 2MB:  0-7 Wch | 8-15 Wcl | 16-23 Wsh | 24-31 Wsl

__constant__ int c_aS1[NCH1] = {0,1,2,3, 4,5,6,7, 8,9,10,11, 12,13,14,15, 0,1,2,3, 4,5,6,7};
__constant__ int c_bS1[NCH1] = {0,1,2,3, 4,5,6,7, 0,1,2,3, 4,5,6,7, 8,9,10,11, 12,13,14,15};
__constant__ int c_aS3[NCH3] = {0,1,2,3,4,5,6,7, 0,1,2,3,4,5,6,7, 8,9,10,11,12,13,14,15,
                                16,17,18,19,20,21,22,23, 16,17,18,19,20,21,22,23, 24,25,26,27,28,29,30,31};
__constant__ int c_bS3[NCH3] = {0,1,2,3,4,5,6,7, 8,9,10,11,12,13,14,15, 0,1,2,3,4,5,6,7,
                                16,17,18,19,20,21,22,23, 24,25,26,27,28,29,30,31, 16,17,18,19,20,21,22,23};

// ---------------- helpers ----------------
__device__ __forceinline__ uint32_t smem_to_u32(const void* p) {
    uint32_t a;
    asm("{ .reg .u64 t; cvta.to.shared.u64 t, %1; cvt.u32.u64 %0, t; }" : "=r"(a) : "l"(p));
    return a;
}
__device__ __forceinline__ void cp16(uint32_t saddr, const void* gaddr) {
    asm volatile("cp.async.cg.shared.global [%0], [%1], 16;" :: "r"(saddr), "l"(gaddr));
}
#define CP_COMMIT() asm volatile("cp.async.commit_group;" ::: "memory")
#define CP_WAIT(n)  asm volatile("cp.async.wait_group %0;" :: "n"(n) : "memory")

__device__ __forceinline__ void ldsm_x4(uint32_t& r0, uint32_t& r1, uint32_t& r2, uint32_t& r3, uint32_t addr) {
    asm volatile("ldmatrix.sync.aligned.m8n8.x4.shared.b16 {%0,%1,%2,%3}, [%4];"
                 : "=r"(r0), "=r"(r1), "=r"(r2), "=r"(r3) : "r"(addr));
}
__device__ __forceinline__ void mma16816(float* d, const uint32_t* a, uint32_t b0, uint32_t b1) {
    asm volatile("mma.sync.aligned.m16n8k16.row.col.f32.bf16.bf16.f32 "
                 "{%0,%1,%2,%3},{%4,%5,%6,%7},{%8,%9},{%0,%1,%2,%3};"
                 : "+f"(d[0]), "+f"(d[1]), "+f"(d[2]), "+f"(d[3])
                 : "r"(a[0]), "r"(a[1]), "r"(a[2]), "r"(a[3]), "r"(b0), "r"(b1));
}
__device__ __forceinline__ unsigned short bfb(float x) {
    __nv_bfloat16 h = __float2bfloat16_rn(x);
    return *reinterpret_cast<unsigned short*>(&h);
}
__device__ __forceinline__ void split_bf(float x, unsigned short& hi, unsigned short& lo) {
    __nv_bfloat16 h = __float2bfloat16_rn(x);
    hi = *reinterpret_cast<unsigned short*>(&h);
    lo = bfb(x - __bfloat162float(h));
}
__device__ __forceinline__ int swz(int row, int col) {
    int b = row * 128 + col * 2;
    return b ^ ((b >> 3) & 0x70);
}

// ---------------- setup (windows + trig LUT) ----------------
__global__ void k_setup() {
    __shared__ float sd[256];
    int tid = threadIdx.x;
    double s = 0.0;
    for (int r = 0; r < 4; r++) {
        int i = r * 256 + tid;
        if (i < WIN) { double w = 0.5 - 0.5 * cospi(2.0 * (double)i / 1022.0); s += w * w; }
    }
    sd[tid] = (float)s;
    __syncthreads();
    for (int n = tid; n < 1024; n += 256) {
        if (n < WIN) {
            double w = 0.5 - 0.5 * cospi(2.0 * (double)n / 1022.0);
            g_window[n] = (float)w;
            g_synth[n] = (float)(w / (double)sd[n & 255]);
        } else g_window[n] = 0.0f;
    }
    for (int j = tid; j < 1022; j += 256) {
        float sn, cs;
        sincospif((float)j / 511.0f, &sn, &cs);
        g_trig[j] = make_float2(cs, sn);
    }
}

// ---------------- B1: folded irfft weights, split, 16 blobs per n-tile ----------------
__global__ void k_fill_w1() {
    int m = blockIdx.x;          // 0..511
    int k = threadIdx.x;         // 0..255
    const float invN = 1.0f / 1022.0f;
    float vc = 0.0f, vs = 0.0f;
    if (m < 511) {
        float sv = g_synth[2 * m];
        if (k == 0) vc = invN * sv;
        else {
            int r = (k * m) % 511;
            float2 t = g_trig[2 * r];
            vc = 2.0f * invN * t.x * sv;
            vs = -2.0f * invN * t.y * sv;
        }
    }
    unsigned short ch, cl, sh, sl;
    split_bf(vc, ch, cl);
    split_bf(vs, sh, sl);
    char* base = g_B1cat + (size_t)(m >> 7) * 16 * BLOB;
    int chunk = k >> 6, off = swz(m & 127, k & 63);
    *(unsigned short*)(base + (chunk) * BLOB + off) = ch;
    *(unsigned short*)(base + (4 + chunk) * BLOB + off) = sh;
    *(unsigned short*)(base + (8 + chunk) * BLOB + off) = cl;
    *(unsigned short*)(base + (12 + chunk) * BLOB + off) = sl;
}

// ---------------- B3: rfft weights, split, 32 blobs per k-tile ----------------
__global__ void k_fill_w3() {
    int kb = blockIdx.x;         // 0..511
    char* base = g_B3cat + (size_t)(kb >> 7) * 32 * BLOB;
    int row = kb & 127;
    for (int n = threadIdx.x; n < 512; n += 256) {
        int j = (n * kb) % WIN;
        float2 t = g_trig[j];
        unsigned short ch, cl, sh, sl;
        split_bf(t.x, ch, cl);
        split_bf(-t.y, sh, sl);
        int chunk = n >> 6, off = swz(row, n & 63);
        *(unsigned short*)(base + (chunk) * BLOB + off) = ch;
        *(unsigned short*)(base + (8 + chunk) * BLOB + off) = cl;
        *(unsigned short*)(base + (16 + chunk) * BLOB + off) = sh;
        *(unsigned short*)(base + (24 + chunk) * BLOB + off) = sl;
    }
}

// ---------------- fold1: spectrum fold, split, 16 blobs per f-tile ----------------
__global__ void k_fold1(const float2* __restrict__ inF2) {
    __shared__ ushort4 tile[32][33];
    int f0 = blockIdx.x * 32;    // 0..8096
    int k0 = blockIdx.y * 32;    // 0..224
    int lx = threadIdx.x & 31, ly = threadIdx.x >> 5;
    int f = f0 + lx;
    int b = f / 127, t = f - b * 127;
#pragma unroll
    for (int q = 0; q < 4; q++) {
        int k = k0 + ly + 8 * q;
        float2 x0 = inF2[(b * 512 + k) * 127 + t];
        float2 x1 = inF2[(b * 512 + 511 - k) * 127 + t];
        float xr = x0.x + x1.x, xi = x0.y - x1.y;
        ushort4 v;
        split_bf(xr, v.x, v.z);
        split_bf(xi, v.y, v.w);
        tile[ly + 8 * q][lx] = v;
    }
    __syncthreads();
    char* base = g_A1cat + (size_t)(f0 >> 7) * 16 * BLOB;
    int row0 = f0 & 127;
    int kk = k0 + lx;
    int chunk = kk >> 6, col = kk & 63;
#pragma unroll
    for (int q = 0; q < 4; q++) {
        int fl = ly + 8 * q;
        ushort4 v = tile[lx][fl];
        int off = swz(row0 + fl, col);
        *(unsigned short*)(base + (chunk) * BLOB + off) = v.x;        // Arh
        *(unsigned short*)(base + (4 + chunk) * BLOB + off) = v.y;    // Aih
        *(unsigned short*)(base + (8 + chunk) * BLOB + off) = v.z;    // Arl
        *(unsigned short*)(base + (12 + chunk) * BLOB + off) = v.w;   // Ail
    }
}

// ---------------- GEMM 1: frames[f][m], M=128 f x N=128 m, depth-3 pipeline ----------------
__global__ void __launch_bounds__(256, 2) k_mma1() {
    extern __shared__ char smem[];
    uint32_t sb = smem_to_u32(smem);
    int tid = threadIdx.x, lane = tid & 31, wid = tid >> 5;
    int wm = wid >> 2, wn = wid & 3;
    int ntile = blockIdx.x;      // m tile 0..3
    int ftile = blockIdx.y;      // f tile 0..63
    const char* Ab = g_A1cat + (size_t)ftile * 16 * BLOB;
    const char* Bb = g_B1cat + (size_t)ntile * 16 * BLOB;

    float acc[4][4][4];
#pragma unroll
    for (int i = 0; i < 4; i++)
#pragma unroll
        for (int j = 0; j < 4; j++)
#pragma unroll
            for (int e = 0; e < 4; e++) acc[i][j][e] = 0.0f;

#define STAGE1(c) do { \
        uint32_t d = sb + ((c) % 3) * CH1_BYTES; \
        const char* ga = Ab + (size_t)c_aS1[(c)] * BLOB; \
        const char* gb = Bb + (size_t)c_bS1[(c)] * BLOB; \
        _Pragma("unroll") \
        for (int r = 0; r < 4; r++) { \
            int e = tid + 256 * r; \
            cp16(d + e * 16, ga + e * 16); \
            cp16(d + 16384 + e * 16, gb + e * 16); \
        } \
        CP_COMMIT(); \
    } while (0)

    STAGE1(0); STAGE1(1);
    int S = 2;
    for (int c = 0; c < NCH1; c++) {
        if (S < NCH1) { STAGE1(S); S++; }
        int pend = S - 1 - c;
        if (pend >= 2) CP_WAIT(2); else if (pend == 1) CP_WAIT(1); else CP_WAIT(0);
        __syncthreads();
        uint32_t SA = sb + (c % 3) * CH1_BYTES, SB = SA + 16384;
#pragma unroll
        for (int k0 = 0; k0 < 64; k0 += 16) {
            uint32_t af[4][4], bf[2][4];
            int colu = k0 + ((lane >> 4) << 3);
#pragma unroll
            for (int i = 0; i < 4; i++) {
                int row = wm * 64 + i * 16 + (lane & 15);
                ldsm_x4(af[i][0], af[i][1], af[i][2], af[i][3], SA + swz(row, colu));
            }
#pragma unroll
            for (int j2 = 0; j2 < 2; j2++) {
                int row = wn * 32 + j2 * 16 + (lane & 15);
                ldsm_x4(bf[j2][0], bf[j2][1], bf[j2][2], bf[j2][3], SB + swz(row, colu));
            }
#pragma unroll
            for (int i = 0; i < 4; i++)
#pragma unroll
                for (int j = 0; j < 4; j++)
                    mma16816(acc[i][j], af[i], bf[j >> 1][j & 1], bf[j >> 1][(j & 1) + 2]);
        }
        __syncthreads();
    }
    int g = lane >> 2, t4 = lane & 3;
#pragma unroll
    for (int i = 0; i < 4; i++) {
        int f0 = ftile * 128 + wm * 64 + i * 16 + g;
#pragma unroll
        for (int j = 0; j < 4; j++) {
            int col = ntile * 128 + wn * 32 + j * 8 + t4 * 2;
            if (f0 < NF)
                *(float2*)(g_frames + (size_t)f0 * 512 + col) = make_float2(acc[i][j][0], acc[i][j][1]);
            if (f0 + 8 < NF)
                *(float2*)(g_frames + (size_t)(f0 + 8) * 512 + col) = make_float2(acc[i][j][2], acc[i][j][3]);
        }
    }
}

// ---------------- pass 1b: odd tail of frame 126 (LUT) ----------------
__global__ void k_pass1b(const float2* __restrict__ inF2) {
    __shared__ float2 sbuf[512];
    __shared__ float part[31][8];
    int b = blockIdx.x;
    int tid = threadIdx.x;
    for (int k = tid; k < 512; k += 256)
        sbuf[k] = inF2[(b * 512 + k) * 127 + 126];
    __syncthreads();
    int ni = tid >> 3, kp = tid & 7;
    if (ni < 31) {
        int n = 961 + 2 * ni;
        float acc = 0.0f;
        for (int k = kp; k < 512; k += 8) {
            float2 x = sbuf[k];
            float2 t = g_trig[(n * k) % WIN];
            float coef = (k == 0 || k == 511) ? 1.0f : 2.0f;
            acc += coef * (x.x * t.x - x.y * t.y);
        }
        part[ni][kp] = acc;
    }
    __syncthreads();
    if (tid < 31) {
        float s = 0.0f;
#pragma unroll
        for (int q = 0; q < 8; q++) s += part[tid][q];
        g_tail[b * 32 + tid] = s * (1.0f / 1022.0f) * g_synth[961 + 2 * tid];
    }
}

// ---------------- pass 2: overlap-add ----------------
__global__ void k_pass2() {
    int idx = blockIdx.x * blockDim.x + threadIdx.x;
    if (idx >= BATCH * L_OUT) return;
    int b = idx / L_OUT, j = idx - b * L_OUT;
    float v;
    if (j < J_EVEN) {
        int p = 2 * j;
        int t_hi = min(126, p >> 8);
        int t_lo = max(0, p - 766) >> 8;
        float acc = 0.0f;
        for (int t = t_lo; t <= t_hi; t++) {
            int m = j - (t << 7);
            acc += g_frames[(b * 127 + t) * 512 + m];
        }
        v = acc;
    } else {
        int n = j - 15648;
        if (n & 1) v = g_tail[b * 32 + ((n - 961) >> 1)];
        else       v = g_frames[(b * 127 + 126) * 512 + (n >> 1)];
    }
    g_sig[b * SIG_STRIDE + j] = v;
}

// ---------------- fold3: window + symmetry fold, split, 32 blobs per f-128-group ----------------
__global__ void k_fold3() {
    __shared__ ushort4 tile[32][33];
    int f0 = blockIdx.x * 32;    // 0..3936
    int n0 = blockIdx.y * 32;    // 0..480
    int lx = threadIdx.x & 31, ly = threadIdx.x >> 5;
    int f = f0 + lx;
    int b = f / 62, t = f - b * 62;
    int bs = b * SIG_STRIDE + t * 256;
#pragma unroll
    for (int q = 0; q < 4; q++) {
        int n = n0 + ly + 8 * q;
        float y = g_sig[bs + n];
        float yp = (n >= 1 && n <= 510) ? g_sig[bs + 1022 - n] : 0.0f;
        float w = g_window[n];
        ushort4 v;
        split_bf(w * (y + yp), v.x, v.y);
        split_bf(w * (y - yp), v.z, v.w);
        tile[ly + 8 * q][lx] = v;
    }
    __syncthreads();
    char* base = g_A3cat + (size_t)(f0 >> 7) * 32 * BLOB;
    int row0 = f0 & 127;
    int nn = n0 + lx;
    int chunk = nn >> 6, col = nn & 63;
#pragma unroll
    for (int q = 0; q < 4; q++) {
        int fl = ly + 8 * q;
        ushort4 v = tile[lx][fl];
        int off = swz(row0 + fl, col);
        *(unsigned short*)(base + (chunk) * BLOB + off) = v.x;        // zeh
        *(unsigned short*)(base + (8 + chunk) * BLOB + off) = v.y;    // zel
        *(unsigned short*)(base + (16 + chunk) * BLOB + off) = v.z;   // zoh
        *(unsigned short*)(base + (24 + chunk) * BLOB + off) = v.w;   // zol
    }
}

// ---------------- GEMM 3: S[k][f], M=128 k x N=64 f, depth-3 pipeline ----------------
__global__ void __launch_bounds__(256, 2) k_mma3(float2* __restrict__ outF2) {
    extern __shared__ char smem[];
    uint32_t sb = smem_to_u32(smem);
    int tid = threadIdx.x, lane = tid & 31, wid = tid >> 5;
    int wm = wid >> 1, wn = wid & 1;     // 4 x 2 warps: M 32/warp, N 32/warp
    int ftile = blockIdx.x;      // f tile 0..61 (64 frames each)
    int ktile = blockIdx.y;      // k tile 0..3
    const char* Ab = g_B3cat + (size_t)ktile * 32 * BLOB;
    const char* Bb = g_A3cat + (size_t)(ftile >> 1) * 32 * BLOB;
    int halfoff = (ftile & 1) * 8192;

    float acc[2][4][4], sv[2][4][4];
#pragma unroll
    for (int i = 0; i < 2; i++)
#pragma unroll
        for (int j = 0; j < 4; j++)
#pragma unroll
            for (int e = 0; e < 4; e++) acc[i][j][e] = 0.0f;

#define STAGE3(c) do { \
        uint32_t d = sb + ((c) % 3) * CH3_BYTES; \
        const char* ga = Ab + (size_t)c_aS3[(c)] * BLOB; \
        const char* gb = Bb + (size_t)c_bS3[(c)] * BLOB + halfoff; \
        _Pragma("unroll") \
        for (int r = 0; r < 4; r++) { \
            int e = tid + 256 * r; \
            cp16(d + e * 16, ga + e * 16); \
        } \
        _Pragma("unroll") \
        for (int r = 0; r < 2; r++) { \
            int e = tid + 256 * r; \
            cp16(d + 16384 + e * 16, gb + e * 16); \
        } \
        CP_COMMIT(); \
    } while (0)

    STAGE3(0); STAGE3(1);
    int S = 2;
    for (int c = 0; c < NCH3; c++) {
        if (S < NCH3) { STAGE3(S); S++; }
        int pend = S - 1 - c;
        if (pend >= 2) CP_WAIT(2); else if (pend == 1) CP_WAIT(1); else CP_WAIT(0);
        __syncthreads();
        uint32_t SA = sb + (c % 3) * CH3_BYTES, SB = SA + 16384;
#pragma unroll
        for (int k0 = 0; k0 < 64; k0 += 16) {
            uint32_t af[2][4], bf[2][4];
            int colu = k0 + ((lane >> 4) << 3);
#pragma unroll
            for (int i = 0; i < 2; i++) {
                int row = wm * 32 + i * 16 + (lane & 15);
                ldsm_x4(af[i][0], af[i][1], af[i][2], af[i][3], SA + swz(row, colu));
            }
#pragma unroll
            for (int j2 = 0; j2 < 2; j2++) {
                int row = wn * 32 + j2 * 16 + (lane & 15);
                ldsm_x4(bf[j2][0], bf[j2][1], bf[j2][2], bf[j2][3], SB + swz(row, colu));
            }
#pragma unroll
            for (int i = 0; i < 2; i++)
#pragma unroll
                for (int j = 0; j < 4; j++)
                    mma16816(acc[i][j], af[i], bf[j >> 1][j & 1], bf[j >> 1][(j & 1) + 2]);
        }
        __syncthreads();
        if (c == 23) {   // end of re chain
#pragma unroll
            for (int i = 0; i < 2; i++)
#pragma unroll
                for (int j = 0; j < 4; j++)
#pragma unroll
                    for (int e = 0; e < 4; e++) { sv[i][j][e] = acc[i][j][e]; acc[i][j][e] = 0.0f; }
        }
    }
    int g = lane >> 2, t4 = lane & 3;
#pragma unroll
    for (int i = 0; i < 2; i++) {
        int kb = ktile * 128 + wm * 32 + i * 16 + g;
#pragma unroll
        for (int j = 0; j < 4; j++) {
            int fc = ftile * 64 + wn * 32 + j * 8 + t4 * 2;
            int b0 = fc / 62, t0 = fc - b0 * 62;
            int b1 = (fc + 1) / 62, t1 = fc + 1 - b1 * 62;
            outF2[((size_t)b0 * 512 + kb) * 62 + t0] = make_float2(sv[i][j][0], acc[i][j][0]);
            outF2[((size_t)b1 * 512 + kb) * 62 + t1] = make_float2(sv[i][j][1], acc[i][j][1]);
            outF2[((size_t)b0 * 512 + kb + 8) * 62 + t0] = make_float2(sv[i][j][2], acc[i][j][2]);
            outF2[((size_t)b1 * 512 + kb + 8) * 62 + t1] = make_float2(sv[i][j][3], acc[i][j][3]);
        }
    }
}

// ---------------- launch ----------------
extern "C" void kernel_launch(void* const* d_in, const int* in_sizes, int n_in,
                              void* d_out, int out_size) {
    (void)in_sizes; (void)n_in; (void)out_size;
    const float2* inF2 = (const float2*)d_in[0];
    float2* outF2 = (float2*)d_out;

    cudaFuncSetAttribute(k_mma1, cudaFuncAttributeMaxDynamicSharedMemorySize, 3 * CH1_BYTES);
    cudaFuncSetAttribute(k_mma3, cudaFuncAttributeMaxDynamicSharedMemorySize, 3 * CH3_BYTES);

    k_setup<<<1, 256>>>();
    k_fill_w1<<<512, 256>>>();
    k_fill_w3<<<512, 256>>>();
    k_fold1<<<dim3(254, 8), 256>>>(inF2);
    k_mma1<<<dim3(4, 64), 256, 3 * CH1_BYTES>>>();
    k_pass1b<<<64, 256>>>(inF2);
    k_pass2<<<(BATCH * L_OUT + 255) / 256, 256>>>();
    k_fold3<<<dim3(124, 16), 256>>>();
    k_mma3<<<dim3(62, 4), 256, 3 * CH3_BYTES>>>(outF2);
}

// round 10
// speedup vs baseline: 4.6362x; 1.2430x over previous
#include <cuda_runtime.h>
#include <cuda_fp16.h>
#include <cstdint>

#define WIN 1022
#define T_IN 127
#define BATCH 64
#define NF (BATCH * T_IN)       // 8128
#define HOP 256
#define T_OUT 62
#define NF3 (BATCH * T_OUT)     // 3968
#define SIG_STRIDE 16672
#define L_OUT 16670
#define J_EVEN 16608

#define BLOB 16384              // one 128row x 64col fp16 SW128 tile
#define NCH1 16                 // pass1 schedule steps (fp16 2-chain)
#define NCH3 32                 // pass3 schedule steps (re 0-15, im 16-31)
#define CH1_BYTES 32768         // A 16K + B 16K
#define CH3_BYTES 24576         // A 16K + B 8K

// ---------------- device scratch ----------------
__device__ float  g_frames[NF * 512];
__device__ float  g_tail[BATCH * 32];
__device__ float  g_sig[BATCH * SIG_STRIDE];
__device__ float2 g_trig[1022];
__device__ float  g_synth[WIN];
__device__ float  g_window[1024];
__device__ __align__(16) char g_A1cat[64 * 8 * BLOB];    // 8MB: 0-3 Arh | 4-7 Aih
__device__ __align__(16) char g_B1cat[4 * 16 * BLOB];    // 1MB: 0-3 Bch | 4-7 Bsh | 8-11 Bcl | 12-15 Bsl
__device__ __align__(16) char g_A3cat[31 * 16 * BLOB];   // 8MB: 0-7 zeh | 8-15 zoh
__device__ __align__(16) char g_B3cat[4 * 32 * BLOB];    // 2MB: 0-7 Wch | 8-15 Wcl | 16-23 Wsh | 24-31 Wsl

__constant__ int c_aS1[NCH1] = {0,1,2,3, 4,5,6,7, 0,1,2,3, 4,5,6,7};
__constant__ int c_bS1[NCH1] = {0,1,2,3, 4,5,6,7, 8,9,10,11, 12,13,14,15};
__constant__ int c_aS3[NCH3] = {0,1,2,3,4,5,6,7,8,9,10,11,12,13,14,15,
                                16,17,18,19,20,21,22,23,24,25,26,27,28,29,30,31}; // W blobs
__constant__ int c_bS3[NCH3] = {0,1,2,3,4,5,6,7, 0,1,2,3,4,5,6,7,
                                8,9,10,11,12,13,14,15, 8,9,10,11,12,13,14,15};     // z blobs

// ---------------- helpers ----------------
__device__ __forceinline__ uint32_t smem_to_u32(const void* p) {
    uint32_t a;
    asm("{ .reg .u64 t; cvta.to.shared.u64 t, %1; cvt.u32.u64 %0, t; }" : "=r"(a) : "l"(p));
    return a;
}
__device__ __forceinline__ void cp16(uint32_t saddr, const void* gaddr) {
    asm volatile("cp.async.cg.shared.global [%0], [%1], 16;" :: "r"(saddr), "l"(gaddr));
}
#define CP_COMMIT() asm volatile("cp.async.commit_group;" ::: "memory")
#define CP_WAIT(n)  asm volatile("cp.async.wait_group %0;" :: "n"(n) : "memory")

__device__ __forceinline__ void ldsm_x4(uint32_t& r0, uint32_t& r1, uint32_t& r2, uint32_t& r3, uint32_t addr) {
    asm volatile("ldmatrix.sync.aligned.m8n8.x4.shared.b16 {%0,%1,%2,%3}, [%4];"
                 : "=r"(r0), "=r"(r1), "=r"(r2), "=r"(r3) : "r"(addr));
}
__device__ __forceinline__ void mma16816(float* d, const uint32_t* a, uint32_t b0, uint32_t b1) {
    asm volatile("mma.sync.aligned.m16n8k16.row.col.f32.f16.f16.f32 "
                 "{%0,%1,%2,%3},{%4,%5,%6,%7},{%8,%9},{%0,%1,%2,%3};"
                 : "+f"(d[0]), "+f"(d[1]), "+f"(d[2]), "+f"(d[3])
                 : "r"(a[0]), "r"(a[1]), "r"(a[2]), "r"(a[3]), "r"(b0), "r"(b1));
}
__device__ __forceinline__ unsigned short hb(float x) {
    __half h = __float2half_rn(x);
    return *reinterpret_cast<unsigned short*>(&h);
}
__device__ __forceinline__ void split_h(float x, unsigned short& hi, unsigned short& lo) {
    __half h = __float2half_rn(x);
    hi = *reinterpret_cast<unsigned short*>(&h);
    lo = hb(x - __half2float(h));
}
__device__ __forceinline__ int swz(int row, int col) {
    int b = row * 128 + col * 2;
    return b ^ ((b >> 3) & 0x70);
}

// ---------------- setup (windows + trig LUT) ----------------
__global__ void k_setup() {
    __shared__ float sd[256];
    int tid = threadIdx.x;
    double s = 0.0;
    for (int r = 0; r < 4; r++) {
        int i = r * 256 + tid;
        if (i < WIN) { double w = 0.5 - 0.5 * cospi(2.0 * (double)i / 1022.0); s += w * w; }
    }
    sd[tid] = (float)s;
    __syncthreads();
    for (int n = tid; n < 1024; n += 256) {
        if (n < WIN) {
            double w = 0.5 - 0.5 * cospi(2.0 * (double)n / 1022.0);
            g_window[n] = (float)w;
            g_synth[n] = (float)(w / (double)sd[n & 255]);
        } else g_window[n] = 0.0f;
    }
    for (int j = tid; j < 1022; j += 256) {
        float sn, cs;
        sincospif((float)j / 511.0f, &sn, &cs);
        g_trig[j] = make_float2(cs, sn);
    }
}

// ---------------- B1: folded irfft weights, fp16 split, 16 blobs per n-tile ----------------
__global__ void k_fill_w1() {
    int m = blockIdx.x;          // 0..511
    int k = threadIdx.x;         // 0..255
    const float invN = 1.0f / 1022.0f;
    float vc = 0.0f, vs = 0.0f;
    if (m < 511) {
        float sv = g_synth[2 * m];
        if (k == 0) vc = invN * sv;
        else {
            int r = (k * m) % 511;
            float2 t = g_trig[2 * r];
            vc = 2.0f * invN * t.x * sv;
            vs = -2.0f * invN * t.y * sv;
        }
    }
    unsigned short ch, cl, sh, sl;
    split_h(vc, ch, cl);
    split_h(vs, sh, sl);
    char* base = g_B1cat + (size_t)(m >> 7) * 16 * BLOB;
    int chunk = k >> 6, off = swz(m & 127, k & 63);
    *(unsigned short*)(base + (chunk) * BLOB + off) = ch;
    *(unsigned short*)(base + (4 + chunk) * BLOB + off) = sh;
    *(unsigned short*)(base + (8 + chunk) * BLOB + off) = cl;
    *(unsigned short*)(base + (12 + chunk) * BLOB + off) = sl;
}

// ---------------- B3: rfft weights, fp16 split, 32 blobs per k-tile ----------------
__global__ void k_fill_w3() {
    int kb = blockIdx.x;         // 0..511
    char* base = g_B3cat + (size_t)(kb >> 7) * 32 * BLOB;
    int row = kb & 127;
    for (int n = threadIdx.x; n < 512; n += 256) {
        int j = (n * kb) % WIN;
        float2 t = g_trig[j];
        unsigned short ch, cl, sh, sl;
        split_h(t.x, ch, cl);
        split_h(-t.y, sh, sl);
        int chunk = n >> 6, off = swz(row, n & 63);
        *(unsigned short*)(base + (chunk) * BLOB + off) = ch;
        *(unsigned short*)(base + (8 + chunk) * BLOB + off) = cl;
        *(unsigned short*)(base + (16 + chunk) * BLOB + off) = sh;
        *(unsigned short*)(base + (24 + chunk) * BLOB + off) = sl;
    }
}

// ---------------- fold1: spectrum fold, fp16 hi only, 8 blobs per f-tile ----------------
__global__ void k_fold1(const float2* __restrict__ inF2) {
    __shared__ ushort2 tile[32][33];
    int f0 = blockIdx.x * 32;    // 0..8096
    int k0 = blockIdx.y * 32;    // 0..224
    int lx = threadIdx.x & 31, ly = threadIdx.x >> 5;
    int f = f0 + lx;
    int b = f / 127, t = f - b * 127;
#pragma unroll
    for (int q = 0; q < 4; q++) {
        int k = k0 + ly + 8 * q;
        float2 x0 = inF2[(b * 512 + k) * 127 + t];
        float2 x1 = inF2[(b * 512 + 511 - k) * 127 + t];
        ushort2 v;
        v.x = hb(x0.x + x1.x);   // Arh
        v.y = hb(x0.y - x1.y);   // Aih
        tile[ly + 8 * q][lx] = v;
    }
    __syncthreads();
    char* base = g_A1cat + (size_t)(f0 >> 7) * 8 * BLOB;
    int row0 = f0 & 127;
    int kk = k0 + lx;
    int chunk = kk >> 6, col = kk & 63;
#pragma unroll
    for (int q = 0; q < 4; q++) {
        int fl = ly + 8 * q;
        ushort2 v = tile[lx][fl];
        int off = swz(row0 + fl, col);
        *(unsigned short*)(base + (chunk) * BLOB + off) = v.x;
        *(unsigned short*)(base + (4 + chunk) * BLOB + off) = v.y;
    }
}

// ---------------- GEMM 1: frames[f][m], M=128 f x N=128 m, depth-3 pipeline ----------------
__global__ void __launch_bounds__(256, 2) k_mma1() {
    extern __shared__ char smem[];
    uint32_t sb = smem_to_u32(smem);
    int tid = threadIdx.x, lane = tid & 31, wid = tid >> 5;
    int wm = wid >> 2, wn = wid & 3;
    int ntile = blockIdx.x;      // m tile 0..3
    int ftile = blockIdx.y;      // f tile 0..63
    const char* Ab = g_A1cat + (size_t)ftile * 8 * BLOB;
    const char* Bb = g_B1cat + (size_t)ntile * 16 * BLOB;

    float acc[4][4][4];
#pragma unroll
    for (int i = 0; i < 4; i++)
#pragma unroll
        for (int j = 0; j < 4; j++)
#pragma unroll
            for (int e = 0; e < 4; e++) acc[i][j][e] = 0.0f;

#define STAGE1(c) do { \
        uint32_t d = sb + ((c) % 3) * CH1_BYTES; \
        const char* ga = Ab + (size_t)c_aS1[(c)] * BLOB; \
        const char* gb = Bb + (size_t)c_bS1[(c)] * BLOB; \
        _Pragma("unroll") \
        for (int r = 0; r < 4; r++) { \
            int e = tid + 256 * r; \
            cp16(d + e * 16, ga + e * 16); \
            cp16(d + 16384 + e * 16, gb + e * 16); \
        } \
        CP_COMMIT(); \
    } while (0)

    STAGE1(0); STAGE1(1);
    int S = 2;
    for (int c = 0; c < NCH1; c++) {
        if (S < NCH1) { STAGE1(S); S++; }
        int pend = S - 1 - c;
        if (pend >= 2) CP_WAIT(2); else if (pend == 1) CP_WAIT(1); else CP_WAIT(0);
        __syncthreads();
        uint32_t SA = sb + (c % 3) * CH1_BYTES, SB = SA + 16384;
#pragma unroll
        for (int k0 = 0; k0 < 64; k0 += 16) {
            uint32_t af[4][4], bf[2][4];
            int colu = k0 + ((lane >> 4) << 3);
#pragma unroll
            for (int i = 0; i < 4; i++) {
                int row = wm * 64 + i * 16 + (lane & 15);
                ldsm_x4(af[i][0], af[i][1], af[i][2], af[i][3], SA + swz(row, colu));
            }
#pragma unroll
            for (int j2 = 0; j2 < 2; j2++) {
                int row = wn * 32 + j2 * 16 + (lane & 15);
                ldsm_x4(bf[j2][0], bf[j2][1], bf[j2][2], bf[j2][3], SB + swz(row, colu));
            }
#pragma unroll
            for (int i = 0; i < 4; i++)
#pragma unroll
                for (int j = 0; j < 4; j++)
                    mma16816(acc[i][j], af[i], bf[j >> 1][j & 1], bf[j >> 1][(j & 1) + 2]);
        }
        __syncthreads();
    }
    int g = lane >> 2, t4 = lane & 3;
#pragma unroll
    for (int i = 0; i < 4; i++) {
        int f0 = ftile * 128 + wm * 64 + i * 16 + g;
#pragma unroll
        for (int j = 0; j < 4; j++) {
            int col = ntile * 128 + wn * 32 + j * 8 + t4 * 2;
            if (f0 < NF)
                *(float2*)(g_frames + (size_t)f0 * 512 + col) = make_float2(acc[i][j][0], acc[i][j][1]);
            if (f0 + 8 < NF)
                *(float2*)(g_frames + (size_t)(f0 + 8) * 512 + col) = make_float2(acc[i][j][2], acc[i][j][3]);
        }
    }
}

// ---------------- pass 1b: odd tail of frame 126 (LUT, fp32) ----------------
__global__ void k_pass1b(const float2* __restrict__ inF2) {
    __shared__ float2 sbuf[512];
    __shared__ float part[31][8];
    int b = blockIdx.x;
    int tid = threadIdx.x;
    for (int k = tid; k < 512; k += 256)
        sbuf[k] = inF2[(b * 512 + k) * 127 + 126];
    __syncthreads();
    int ni = tid >> 3, kp = tid & 7;
    if (ni < 31) {
        int n = 961 + 2 * ni;
        float acc = 0.0f;
        for (int k = kp; k < 512; k += 8) {
            float2 x = sbuf[k];
            float2 t = g_trig[(n * k) % WIN];
            float coef = (k == 0 || k == 511) ? 1.0f : 2.0f;
            acc += coef * (x.x * t.x - x.y * t.y);
        }
        part[ni][kp] = acc;
    }
    __syncthreads();
    if (tid < 31) {
        float s = 0.0f;
#pragma unroll
        for (int q = 0; q < 8; q++) s += part[tid][q];
        g_tail[b * 32 + tid] = s * (1.0f / 1022.0f) * g_synth[961 + 2 * tid];
    }
}

// ---------------- pass 2: overlap-add ----------------
__global__ void k_pass2() {
    int idx = blockIdx.x * blockDim.x + threadIdx.x;
    if (idx >= BATCH * L_OUT) return;
    int b = idx / L_OUT, j = idx - b * L_OUT;
    float v;
    if (j < J_EVEN) {
        int p = 2 * j;
        int t_hi = min(126, p >> 8);
        int t_lo = max(0, p - 766) >> 8;
        float acc = 0.0f;
        for (int t = t_lo; t <= t_hi; t++) {
            int m = j - (t << 7);
            acc += g_frames[(b * 127 + t) * 512 + m];
        }
        v = acc;
    } else {
        int n = j - 15648;
        if (n & 1) v = g_tail[b * 32 + ((n - 961) >> 1)];
        else       v = g_frames[(b * 127 + 126) * 512 + (n >> 1)];
    }
    g_sig[b * SIG_STRIDE + j] = v;
}

// ---------------- fold3: window + symmetry fold, fp16 hi only, 16 blobs per f-group ----------------
__global__ void k_fold3() {
    __shared__ ushort2 tile[32][33];
    int f0 = blockIdx.x * 32;    // 0..3936
    int n0 = blockIdx.y * 32;    // 0..480
    int lx = threadIdx.x & 31, ly = threadIdx.x >> 5;
    int f = f0 + lx;
    int b = f / 62, t = f - b * 62;
    int bs = b * SIG_STRIDE + t * 256;
#pragma unroll
    for (int q = 0; q < 4; q++) {
        int n = n0 + ly + 8 * q;
        float y = g_sig[bs + n];
        float yp = (n >= 1 && n <= 510) ? g_sig[bs + 1022 - n] : 0.0f;
        float w = g_window[n];
        ushort2 v;
        v.x = hb(w * (y + yp));  // zeh
        v.y = hb(w * (y - yp));  // zoh
        tile[ly + 8 * q][lx] = v;
    }
    __syncthreads();
    char* base = g_A3cat + (size_t)(f0 >> 7) * 16 * BLOB;
    int row0 = f0 & 127;
    int nn = n0 + lx;
    int chunk = nn >> 6, col = nn & 63;
#pragma unroll
    for (int q = 0; q < 4; q++) {
        int fl = ly + 8 * q;
        ushort2 v = tile[lx][fl];
        int off = swz(row0 + fl, col);
        *(unsigned short*)(base + (chunk) * BLOB + off) = v.x;
        *(unsigned short*)(base + (8 + chunk) * BLOB + off) = v.y;
    }
}

// ---------------- GEMM 3: S[k][f], M=128 k x N=64 f, depth-3 pipeline ----------------
__global__ void __launch_bounds__(256, 2) k_mma3(float2* __restrict__ outF2) {
    extern __shared__ char smem[];
    uint32_t sb = smem_to_u32(smem);
    int tid = threadIdx.x, lane = tid & 31, wid = tid >> 5;
    int wm = wid >> 1, wn = wid & 1;     // 4 x 2 warps: M 32/warp, N 32/warp
    int ftile = blockIdx.x;      // f tile 0..61 (64 frames each)
    int ktile = blockIdx.y;      // k tile 0..3
    const char* Ab = g_B3cat + (size_t)ktile * 32 * BLOB;
    const char* Bb = g_A3cat + (size_t)(ftile >> 1) * 16 * BLOB;
    int halfoff = (ftile & 1) * 8192;

    float acc[2][4][4], sv[2][4][4];
#pragma unroll
    for (int i = 0; i < 2; i++)
#pragma unroll
        for (int j = 0; j < 4; j++)
#pragma unroll
            for (int e = 0; e < 4; e++) acc[i][j][e] = 0.0f;

#define STAGE3(c) do { \
        uint32_t d = sb + ((c) % 3) * CH3_BYTES; \
        const char* ga = Ab + (size_t)c_aS3[(c)] * BLOB; \
        const char* gb = Bb + (size_t)c_bS3[(c)] * BLOB + halfoff; \
        _Pragma("unroll") \
        for (int r = 0; r < 4; r++) { \
            int e = tid + 256 * r; \
            cp16(d + e * 16, ga + e * 16); \
        } \
        _Pragma("unroll") \
        for (int r = 0; r < 2; r++) { \
            int e = tid + 256 * r; \
            cp16(d + 16384 + e * 16, gb + e * 16); \
        } \
        CP_COMMIT(); \
    } while (0)

    STAGE3(0); STAGE3(1);
    int S = 2;
    for (int c = 0; c < NCH3; c++) {
        if (S < NCH3) { STAGE3(S); S++; }
        int pend = S - 1 - c;
        if (pend >= 2) CP_WAIT(2); else if (pend == 1) CP_WAIT(1); else CP_WAIT(0);
        __syncthreads();
        uint32_t SA = sb + (c % 3) * CH3_BYTES, SB = SA + 16384;
#pragma unroll
        for (int k0 = 0; k0 < 64; k0 += 16) {
            uint32_t af[2][4], bf[2][4];
            int colu = k0 + ((lane >> 4) << 3);
#pragma unroll
            for (int i = 0; i < 2; i++) {
                int row = wm * 32 + i * 16 + (lane & 15);
                ldsm_x4(af[i][0], af[i][1], af[i][2], af[i][3], SA + swz(row, colu));
            }
#pragma unroll
            for (int j2 = 0; j2 < 2; j2++) {
                int row = wn * 32 + j2 * 16 + (lane & 15);
                ldsm_x4(bf[j2][0], bf[j2][1], bf[j2][2], bf[j2][3], SB + swz(row, colu));
            }
#pragma unroll
            for (int i = 0; i < 2; i++)
#pragma unroll
                for (int j = 0; j < 4; j++)
                    mma16816(acc[i][j], af[i], bf[j >> 1][j & 1], bf[j >> 1][(j & 1) + 2]);
        }
        __syncthreads();
        if (c == 15) {   // end of re chain
#pragma unroll
            for (int i = 0; i < 2; i++)
#pragma unroll
                for (int j = 0; j < 4; j++)
#pragma unroll
                    for (int e = 0; e < 4; e++) { sv[i][j][e] = acc[i][j][e]; acc[i][j][e] = 0.0f; }
        }
    }
    int g = lane >> 2, t4 = lane & 3;
#pragma unroll
    for (int i = 0; i < 2; i++) {
        int kb = ktile * 128 + wm * 32 + i * 16 + g;
#pragma unroll
        for (int j = 0; j < 4; j++) {
            int fc = ftile * 64 + wn * 32 + j * 8 + t4 * 2;
            int b0 = fc / 62, t0 = fc - b0 * 62;
            int b1 = (fc + 1) / 62, t1 = fc + 1 - b1 * 62;
            outF2[((size_t)b0 * 512 + kb) * 62 + t0] = make_float2(sv[i][j][0], acc[i][j][0]);
            outF2[((size_t)b1 * 512 + kb) * 62 + t1] = make_float2(sv[i][j][1], acc[i][j][1]);
            outF2[((size_t)b0 * 512 + kb + 8) * 62 + t0] = make_float2(sv[i][j][2], acc[i][j][2]);
            outF2[((size_t)b1 * 512 + kb + 8) * 62 + t1] = make_float2(sv[i][j][3], acc[i][j][3]);
        }
    }
}

// ---------------- launch ----------------
extern "C" void kernel_launch(void* const* d_in, const int* in_sizes, int n_in,
                              void* d_out, int out_size) {
    (void)in_sizes; (void)n_in; (void)out_size;
    const float2* inF2 = (const float2*)d_in[0];
    float2* outF2 = (float2*)d_out;

    cudaFuncSetAttribute(k_mma1, cudaFuncAttributeMaxDynamicSharedMemorySize, 3 * CH1_BYTES);
    cudaFuncSetAttribute(k_mma3, cudaFuncAttributeMaxDynamicSharedMemorySize, 3 * CH3_BYTES);

    k_setup<<<1, 256>>>();
    k_fill_w1<<<512, 256>>>();
    k_fill_w3<<<512, 256>>>();
    k_fold1<<<dim3(254, 8), 256>>>(inF2);
    k_mma1<<<dim3(4, 64), 256, 3 * CH1_BYTES>>>();
    k_pass1b<<<64, 256>>>(inF2);
    k_pass2<<<(BATCH * L_OUT + 255) / 256, 256>>>();
    k_fold3<<<dim3(124, 16), 256>>>();
    k_mma3<<<dim3(62, 4), 256, 3 * CH3_BYTES>>>(outF2);
}

// round 11
// speedup vs baseline: 7.4187x; 1.6001x over previous
#include <cuda_runtime.h>
#include <cuda_fp16.h>
#include <cstdint>

#define WIN 1022
#define T_IN 127
#define BATCH 64
#define NF (BATCH * T_IN)       // 8128
#define HOP 256
#define T_OUT 62
#define NF3 (BATCH * T_OUT)     // 3968
#define SIG_STRIDE 16672
#define L_OUT 16670
#define J_EVEN 16608

#define BLOB 16384              // one 128row x 64col fp16 SW128 tile
#define NCH1 8                  // pass1: Ar*Bc (0-3) + Ai*Bs (4-7), hi-only
#define NCH3 16                 // pass3: re = ze*Wc (0-7), im = zo*Ws (8-15), hi-only
#define CH1_BYTES 32768         // A 16K + B 16K
#define CH3_BYTES 24576         // A 16K + B 8K

// ---------------- device scratch ----------------
__device__ float  g_frames[NF * 512];
__device__ float  g_tail[BATCH * 32];
__device__ float  g_sig[BATCH * SIG_STRIDE];
__device__ __align__(16) char g_A1cat[64 * 8 * BLOB];    // 8MB: 0-3 Arh | 4-7 Aih
__device__ __align__(16) char g_B1cat[4 * 8 * BLOB];     // 512KB: 0-3 Bch | 4-7 Bsh
__device__ __align__(16) char g_A3cat[31 * 16 * BLOB];   // 8MB: 0-7 zeh | 8-15 zoh
__device__ __align__(16) char g_B3cat[4 * 16 * BLOB];    // 1MB: 0-7 Wch | 8-15 Wsh

// ---------------- helpers ----------------
__device__ __forceinline__ uint32_t smem_to_u32(const void* p) {
    uint32_t a;
    asm("{ .reg .u64 t; cvta.to.shared.u64 t, %1; cvt.u32.u64 %0, t; }" : "=r"(a) : "l"(p));
    return a;
}
__device__ __forceinline__ void cp16(uint32_t saddr, const void* gaddr) {
    asm volatile("cp.async.cg.shared.global [%0], [%1], 16;" :: "r"(saddr), "l"(gaddr));
}
#define CP_COMMIT() asm volatile("cp.async.commit_group;" ::: "memory")
#define CP_WAIT(n)  asm volatile("cp.async.wait_group %0;" :: "n"(n) : "memory")

__device__ __forceinline__ void ldsm_x4(uint32_t& r0, uint32_t& r1, uint32_t& r2, uint32_t& r3, uint32_t addr) {
    asm volatile("ldmatrix.sync.aligned.m8n8.x4.shared.b16 {%0,%1,%2,%3}, [%4];"
                 : "=r"(r0), "=r"(r1), "=r"(r2), "=r"(r3) : "r"(addr));
}
__device__ __forceinline__ void mma16816(float* d, const uint32_t* a, uint32_t b0, uint32_t b1) {
    asm volatile("mma.sync.aligned.m16n8k16.row.col.f32.f16.f16.f32 "
                 "{%0,%1,%2,%3},{%4,%5,%6,%7},{%8,%9},{%0,%1,%2,%3};"
                 : "+f"(d[0]), "+f"(d[1]), "+f"(d[2]), "+f"(d[3])
                 : "r"(a[0]), "r"(a[1]), "r"(a[2]), "r"(a[3]), "r"(b0), "r"(b1));
}
__device__ __forceinline__ unsigned short hb(float x) {
    __half h = __float2half_rn(x);
    return *reinterpret_cast<unsigned short*>(&h);
}
__device__ __forceinline__ int swz(int row, int col) {
    int b = row * 128 + col * 2;
    return b ^ ((b >> 3) & 0x70);
}
__device__ __forceinline__ float hannf(int x) {   // hann window, x in [0,1022)
    return 0.5f - 0.5f * cospif((float)x / 511.0f);
}

// ---------------- fused table fills (no LUT deps) ----------------
// blocks 0..511: W1 (m = bid); blocks 512..1023: W3 (kb = bid - 512)
__global__ void k_fill() {
    int bid = blockIdx.x;
    if (bid < 512) {
        int m = bid;               // output sample col
        int k = threadIdx.x;       // 0..255
        __shared__ float s_sv;
        if (threadIdx.x == 0) {
            float sv = 0.0f;
            if (m < 511) {
                int i = (2 * m) & 255;
                float d = 0.0f;
#pragma unroll
                for (int q = 0; q < 4; q++) {
                    int x = q * 256 + i;
                    if (x < WIN) { float ww = hannf(x); d += ww * ww; }
                }
                sv = hannf(2 * m) / d;
            }
            s_sv = sv;
        }
        __syncthreads();
        const float invN = 1.0f / 1022.0f;
        float vc = 0.0f, vs = 0.0f;
        if (m < 511) {
            if (k == 0) vc = invN * s_sv;
            else {
                int r = (k * m) % 511;
                float sn, cs;
                sincospif(2.0f * (float)r / 511.0f, &sn, &cs);
                vc = 2.0f * invN * cs * s_sv;
                vs = -2.0f * invN * sn * s_sv;
            }
        }
        char* base = g_B1cat + (size_t)(m >> 7) * 8 * BLOB;
        int chunk = k >> 6, off = swz(m & 127, k & 63);
        *(unsigned short*)(base + (chunk) * BLOB + off) = hb(vc);
        *(unsigned short*)(base + (4 + chunk) * BLOB + off) = hb(vs);
    } else {
        int kb = bid - 512;        // 0..511
        char* base = g_B3cat + (size_t)(kb >> 7) * 16 * BLOB;
        int row = kb & 127;
        for (int n = threadIdx.x; n < 512; n += 256) {
            int j = (n * kb) % WIN;
            float sn, cs;
            sincospif((float)j / 511.0f, &sn, &cs);
            int chunk = n >> 6, off = swz(row, n & 63);
            *(unsigned short*)(base + (chunk) * BLOB + off) = hb(cs);        // Wch
            *(unsigned short*)(base + (8 + chunk) * BLOB + off) = hb(-sn);   // Wsh
        }
    }
}

// ---------------- fold1: spectrum fold, fp16 hi only, 8 blobs per f-tile ----------------
__global__ void k_fold1(const float2* __restrict__ inF2) {
    __shared__ ushort2 tile[32][33];
    int f0 = blockIdx.x * 32;    // 0..8096
    int k0 = blockIdx.y * 32;    // 0..224
    int lx = threadIdx.x & 31, ly = threadIdx.x >> 5;
    int f = f0 + lx;
    int b = f / 127, t = f - b * 127;
#pragma unroll
    for (int q = 0; q < 4; q++) {
        int k = k0 + ly + 8 * q;
        float2 x0 = inF2[(b * 512 + k) * 127 + t];
        float2 x1 = inF2[(b * 512 + 511 - k) * 127 + t];
        ushort2 v;
        v.x = hb(x0.x + x1.x);   // Arh
        v.y = hb(x0.y - x1.y);   // Aih
        tile[ly + 8 * q][lx] = v;
    }
    __syncthreads();
    char* base = g_A1cat + (size_t)(f0 >> 7) * 8 * BLOB;
    int row0 = f0 & 127;
    int kk = k0 + lx;
    int chunk = kk >> 6, col = kk & 63;
#pragma unroll
    for (int q = 0; q < 4; q++) {
        int fl = ly + 8 * q;
        ushort2 v = tile[lx][fl];
        int off = swz(row0 + fl, col);
        *(unsigned short*)(base + (chunk) * BLOB + off) = v.x;
        *(unsigned short*)(base + (4 + chunk) * BLOB + off) = v.y;
    }
}

// ---------------- GEMM 1: frames[f][m], M=128 f x N=128 m, depth-3 pipeline ----------------
__global__ void __launch_bounds__(256, 2) k_mma1() {
    extern __shared__ char smem[];
    uint32_t sb = smem_to_u32(smem);
    int tid = threadIdx.x, lane = tid & 31, wid = tid >> 5;
    int wm = wid >> 2, wn = wid & 3;
    int ntile = blockIdx.x;      // m tile 0..3
    int ftile = blockIdx.y;      // f tile 0..63
    const char* Ab = g_A1cat + (size_t)ftile * 8 * BLOB;
    const char* Bb = g_B1cat + (size_t)ntile * 8 * BLOB;

    float acc[4][4][4];
#pragma unroll
    for (int i = 0; i < 4; i++)
#pragma unroll
        for (int j = 0; j < 4; j++)
#pragma unroll
            for (int e = 0; e < 4; e++) acc[i][j][e] = 0.0f;

#define STAGE1(c) do { \
        uint32_t d = sb + ((c) % 3) * CH1_BYTES; \
        const char* ga = Ab + (size_t)(c) * BLOB; \
        const char* gb = Bb + (size_t)(c) * BLOB; \
        _Pragma("unroll") \
        for (int r = 0; r < 4; r++) { \
            int e = tid + 256 * r; \
            cp16(d + e * 16, ga + e * 16); \
            cp16(d + 16384 + e * 16, gb + e * 16); \
        } \
        CP_COMMIT(); \
    } while (0)

    STAGE1(0); STAGE1(1);
    int S = 2;
    for (int c = 0; c < NCH1; c++) {
        if (S < NCH1) { STAGE1(S); S++; }
        int pend = S - 1 - c;
        if (pend >= 2) CP_WAIT(2); else if (pend == 1) CP_WAIT(1); else CP_WAIT(0);
        __syncthreads();
        uint32_t SA = sb + (c % 3) * CH1_BYTES, SB = SA + 16384;
#pragma unroll
        for (int k0 = 0; k0 < 64; k0 += 16) {
            uint32_t af[4][4], bf[2][4];
            int colu = k0 + ((lane >> 4) << 3);
#pragma unroll
            for (int i = 0; i < 4; i++) {
                int row = wm * 64 + i * 16 + (lane & 15);
                ldsm_x4(af[i][0], af[i][1], af[i][2], af[i][3], SA + swz(row, colu));
            }
#pragma unroll
            for (int j2 = 0; j2 < 2; j2++) {
                int row = wn * 32 + j2 * 16 + (lane & 15);
                ldsm_x4(bf[j2][0], bf[j2][1], bf[j2][2], bf[j2][3], SB + swz(row, colu));
            }
#pragma unroll
            for (int i = 0; i < 4; i++)
#pragma unroll
                for (int j = 0; j < 4; j++)
                    mma16816(acc[i][j], af[i], bf[j >> 1][j & 1], bf[j >> 1][(j & 1) + 2]);
        }
        __syncthreads();
    }
    int g = lane >> 2, t4 = lane & 3;
#pragma unroll
    for (int i = 0; i < 4; i++) {
        int f0 = ftile * 128 + wm * 64 + i * 16 + g;
#pragma unroll
        for (int j = 0; j < 4; j++) {
            int col = ntile * 128 + wn * 32 + j * 8 + t4 * 2;
            if (f0 < NF)
                *(float2*)(g_frames + (size_t)f0 * 512 + col) = make_float2(acc[i][j][0], acc[i][j][1]);
            if (f0 + 8 < NF)
                *(float2*)(g_frames + (size_t)(f0 + 8) * 512 + col) = make_float2(acc[i][j][2], acc[i][j][3]);
        }
    }
}

// ---------------- pass 1b: odd tail of frame 126 (fp32, inline trig) ----------------
__global__ void k_pass1b(const float2* __restrict__ inF2) {
    __shared__ float2 sbuf[512];
    __shared__ float part[31][8];
    int b = blockIdx.x;
    int tid = threadIdx.x;
    for (int k = tid; k < 512; k += 256)
        sbuf[k] = inF2[(b * 512 + k) * 127 + 126];
    __syncthreads();
    int ni = tid >> 3, kp = tid & 7;
    if (ni < 31) {
        int n = 961 + 2 * ni;
        float acc = 0.0f;
        for (int k = kp; k < 512; k += 8) {
            float2 x = sbuf[k];
            int j = (n * k) % WIN;
            float sn, cs;
            sincospif((float)j / 511.0f, &sn, &cs);
            float coef = (k == 0 || k == 511) ? 1.0f : 2.0f;
            acc += coef * (x.x * cs - x.y * sn);
        }
        part[ni][kp] = acc;
    }
    __syncthreads();
    if (tid < 31) {
        float s = 0.0f;
#pragma unroll
        for (int q = 0; q < 8; q++) s += part[tid][q];
        int np = 961 + 2 * tid;
        int i = np & 255;
        float d = 0.0f;
#pragma unroll
        for (int q = 0; q < 4; q++) {
            int x = q * 256 + i;
            if (x < WIN) { float ww = hannf(x); d += ww * ww; }
        }
        g_tail[b * 32 + tid] = s * (1.0f / 1022.0f) * (hannf(np) / d);
    }
}

// ---------------- pass 2: overlap-add ----------------
__global__ void k_pass2() {
    int idx = blockIdx.x * blockDim.x + threadIdx.x;
    if (idx >= BATCH * L_OUT) return;
    int b = idx / L_OUT, j = idx - b * L_OUT;
    float v;
    if (j < J_EVEN) {
        int p = 2 * j;
        int t_hi = min(126, p >> 8);
        int t_lo = max(0, p - 766) >> 8;
        float acc = 0.0f;
        for (int t = t_lo; t <= t_hi; t++) {
            int m = j - (t << 7);
            acc += g_frames[(b * 127 + t) * 512 + m];
        }
        v = acc;
    } else {
        int n = j - 15648;
        if (n & 1) v = g_tail[b * 32 + ((n - 961) >> 1)];
        else       v = g_frames[(b * 127 + 126) * 512 + (n >> 1)];
    }
    g_sig[b * SIG_STRIDE + j] = v;
}

// ---------------- fold3: window + symmetry fold, fp16 hi only, 16 blobs per f-group ----------------
__global__ void k_fold3() {
    __shared__ ushort2 tile[32][33];
    int f0 = blockIdx.x * 32;    // 0..3936
    int n0 = blockIdx.y * 32;    // 0..480
    int lx = threadIdx.x & 31, ly = threadIdx.x >> 5;
    int f = f0 + lx;
    int b = f / 62, t = f - b * 62;
    int bs = b * SIG_STRIDE + t * 256;
#pragma unroll
    for (int q = 0; q < 4; q++) {
        int n = n0 + ly + 8 * q;
        float y = g_sig[bs + n];
        float yp = (n >= 1 && n <= 510) ? g_sig[bs + 1022 - n] : 0.0f;
        float w = hannf(n);
        ushort2 v;
        v.x = hb(w * (y + yp));  // zeh
        v.y = hb(w * (y - yp));  // zoh
        tile[ly + 8 * q][lx] = v;
    }
    __syncthreads();
    char* base = g_A3cat + (size_t)(f0 >> 7) * 16 * BLOB;
    int row0 = f0 & 127;
    int nn = n0 + lx;
    int chunk = nn >> 6, col = nn & 63;
#pragma unroll
    for (int q = 0; q < 4; q++) {
        int fl = ly + 8 * q;
        ushort2 v = tile[lx][fl];
        int off = swz(row0 + fl, col);
        *(unsigned short*)(base + (chunk) * BLOB + off) = v.x;        // zeh
        *(unsigned short*)(base + (8 + chunk) * BLOB + off) = v.y;    // zoh
    }
}

// ---------------- GEMM 3: S[k][f], M=128 k x N=64 f, depth-3 pipeline ----------------
__global__ void __launch_bounds__(256, 2) k_mma3(float2* __restrict__ outF2) {
    extern __shared__ char smem[];
    uint32_t sb = smem_to_u32(smem);
    int tid = threadIdx.x, lane = tid & 31, wid = tid >> 5;
    int wm = wid >> 1, wn = wid & 1;     // 4 x 2 warps
    int ftile = blockIdx.x;      // f tile 0..61 (64 frames each)
    int ktile = blockIdx.y;      // k tile 0..3
    const char* Ab = g_B3cat + (size_t)ktile * 16 * BLOB;        // W blobs: 0-7 Wch, 8-15 Wsh
    const char* Bb = g_A3cat + (size_t)(ftile >> 1) * 16 * BLOB; // z blobs: 0-7 zeh, 8-15 zoh
    int halfoff = (ftile & 1) * 8192;

    float acc[2][4][4], sv[2][4][4];
#pragma unroll
    for (int i = 0; i < 2; i++)
#pragma unroll
        for (int j = 0; j < 4; j++)
#pragma unroll
            for (int e = 0; e < 4; e++) acc[i][j][e] = 0.0f;

#define STAGE3(c) do { \
        uint32_t d = sb + ((c) % 3) * CH3_BYTES; \
        const char* ga = Ab + (size_t)(c) * BLOB; \
        const char* gb = Bb + (size_t)(c) * BLOB + halfoff; \
        _Pragma("unroll") \
        for (int r = 0; r < 4; r++) { \
            int e = tid + 256 * r; \
            cp16(d + e * 16, ga + e * 16); \
        } \
        _Pragma("unroll") \
        for (int r = 0; r < 2; r++) { \
            int e = tid + 256 * r; \
            cp16(d + 16384 + e * 16, gb + e * 16); \
        } \
        CP_COMMIT(); \
    } while (0)

    STAGE3(0); STAGE3(1);
    int S = 2;
    for (int c = 0; c < NCH3; c++) {
        if (S < NCH3) { STAGE3(S); S++; }
        int pend = S - 1 - c;
        if (pend >= 2) CP_WAIT(2); else if (pend == 1) CP_WAIT(1); else CP_WAIT(0);
        __syncthreads();
        uint32_t SA = sb + (c % 3) * CH3_BYTES, SB = SA + 16384;
#pragma unroll
        for (int k0 = 0; k0 < 64; k0 += 16) {
            uint32_t af[2][4], bf[2][4];
            int colu = k0 + ((lane >> 4) << 3);
#pragma unroll
            for (int i = 0; i < 2; i++) {
                int row = wm * 32 + i * 16 + (lane & 15);
                ldsm_x4(af[i][0], af[i][1], af[i][2], af[i][3], SA + swz(row, colu));
            }
#pragma unroll
            for (int j2 = 0; j2 < 2; j2++) {
                int row = wn * 32 + j2 * 16 + (lane & 15);
                ldsm_x4(bf[j2][0], bf[j2][1], bf[j2][2], bf[j2][3], SB + swz(row, colu));
            }
#pragma unroll
            for (int i = 0; i < 2; i++)
#pragma unroll
                for (int j = 0; j < 4; j++)
                    mma16816(acc[i][j], af[i], bf[j >> 1][j & 1], bf[j >> 1][(j & 1) + 2]);
        }
        __syncthreads();
        if (c == 7) {   // end of re chain
#pragma unroll
            for (int i = 0; i < 2; i++)
#pragma unroll
                for (int j = 0; j < 4; j++)
#pragma unroll
                    for (int e = 0; e < 4; e++) { sv[i][j][e] = acc[i][j][e]; acc[i][j][e] = 0.0f; }
        }
    }
    int g = lane >> 2, t4 = lane & 3;
#pragma unroll
    for (int i = 0; i < 2; i++) {
        int kb = ktile * 128 + wm * 32 + i * 16 + g;
#pragma unroll
        for (int j = 0; j < 4; j++) {
            int fc = ftile * 64 + wn * 32 + j * 8 + t4 * 2;
            int b0 = fc / 62, t0 = fc - b0 * 62;
            int b1 = (fc + 1) / 62, t1 = fc + 1 - b1 * 62;
            outF2[((size_t)b0 * 512 + kb) * 62 + t0] = make_float2(sv[i][j][0], acc[i][j][0]);
            outF2[((size_t)b1 * 512 + kb) * 62 + t1] = make_float2(sv[i][j][1], acc[i][j][1]);
            outF2[((size_t)b0 * 512 + kb + 8) * 62 + t0] = make_float2(sv[i][j][2], acc[i][j][2]);
            outF2[((size_t)b1 * 512 + kb + 8) * 62 + t1] = make_float2(sv[i][j][3], acc[i][j][3]);
        }
    }
}

// ---------------- launch ----------------
extern "C" void kernel_launch(void* const* d_in, const int* in_sizes, int n_in,
                              void* d_out, int out_size) {
    (void)in_sizes; (void)n_in; (void)out_size;
    const float2* inF2 = (const float2*)d_in[0];
    float2* outF2 = (float2*)d_out;

    cudaFuncSetAttribute(k_mma1, cudaFuncAttributeMaxDynamicSharedMemorySize, 3 * CH1_BYTES);
    cudaFuncSetAttribute(k_mma3, cudaFuncAttributeMaxDynamicSharedMemorySize, 3 * CH3_BYTES);

    k_fill<<<1024, 256>>>();
    k_fold1<<<dim3(254, 8), 256>>>(inF2);
    k_mma1<<<dim3(4, 64), 256, 3 * CH1_BYTES>>>();
    k_pass1b<<<64, 256>>>(inF2);
    k_pass2<<<(BATCH * L_OUT + 255) / 256, 256>>>();
    k_fold3<<<dim3(124, 16), 256>>>();
    k_mma3<<<dim3(62, 4), 256, 3 * CH3_BYTES>>>(outF2);
}